// round 1
// baseline (speedup 1.0000x reference)
#include <cuda_runtime.h>
#include <math.h>

// Problem constants
constexpr int B_  = 4;
constexpr int C_  = 256;
constexpr int C8_ = 32;
constexpr int N_  = 4096;   // 64*64
constexpr int K_  = 3;

// AV tiling
constexpr int TI = 64;    // query tile
constexpr int TJ = 64;    // key tile
constexpr int TC = 128;   // channel tile

// Scratch (device globals; no allocation allowed)
__device__ float g_k  [(size_t)B_ * C8_ * N_];          // [b][o][n]
__device__ float g_q  [(size_t)K_ * B_ * N_ * C8_];     // [kk][b][n][o]
__device__ float g_v  [(size_t)K_ * B_ * C_ * N_];      // [kk][b][c][n]
__device__ float g_den[(size_t)K_ * B_ * N_];           // [kk][b][i]
__device__ float g_acc[(size_t)B_ * C_ * N_];           // [b][c][n]

// ---------------------------------------------------------------------------
// k = Wk @ x_f + bk   -> g_k[b][o][n]
// ---------------------------------------------------------------------------
__global__ void proj_k_kernel(const float* __restrict__ x,
                              const float* __restrict__ W,
                              const float* __restrict__ bias) {
    __shared__ float Ws[C_ * C8_];  // [c][o]
    int tid = threadIdx.x;
    for (int idx = tid; idx < C_ * C8_; idx += 128) {
        int o = idx >> 8, c = idx & 255;  // W[o*256+c]
        Ws[c * C8_ + o] = W[idx];
    }
    __syncthreads();
    int b = blockIdx.y;
    int n = blockIdx.x * 128 + tid;
    const float* xb = x + (size_t)b * C_ * N_;
    float acc[C8_];
#pragma unroll
    for (int o = 0; o < C8_; o++) acc[o] = bias[o];
    for (int c = 0; c < C_; c++) {
        float xv = xb[c * N_ + n];
#pragma unroll
        for (int o = 0; o < C8_; o++) acc[o] = fmaf(Ws[c * C8_ + o], xv, acc[o]);
    }
    float* out = g_k + (size_t)b * C8_ * N_;
#pragma unroll
    for (int o = 0; o < C8_; o++) out[o * N_ + n] = acc[o];
}

// ---------------------------------------------------------------------------
// q = Wq @ x_b[kk] + bq  -> g_q[kk][b][n][o]  (transposed layout)
// ---------------------------------------------------------------------------
__global__ void proj_q_kernel(const float* __restrict__ xball,
                              const float* __restrict__ W,
                              const float* __restrict__ bias) {
    __shared__ float Ws[C_ * C8_];
    int tid = threadIdx.x;
    for (int idx = tid; idx < C_ * C8_; idx += 128) {
        int o = idx >> 8, c = idx & 255;
        Ws[c * C8_ + o] = W[idx];
    }
    __syncthreads();
    int b = blockIdx.y, kk = blockIdx.z;
    int n = blockIdx.x * 128 + tid;
    const float* xb = xball + (size_t)(kk * B_ + b) * C_ * N_;
    float acc[C8_];
#pragma unroll
    for (int o = 0; o < C8_; o++) acc[o] = bias[o];
    for (int c = 0; c < C_; c++) {
        float xv = xb[c * N_ + n];
#pragma unroll
        for (int o = 0; o < C8_; o++) acc[o] = fmaf(Ws[c * C8_ + o], xv, acc[o]);
    }
    float* op = g_q + ((size_t)(kk * B_ + b) * N_ + n) * C8_;
#pragma unroll
    for (int o = 0; o < C8_; o += 4) {
        float4 v4 = make_float4(acc[o], acc[o + 1], acc[o + 2], acc[o + 3]);
        *(float4*)(op + o) = v4;
    }
}

// ---------------------------------------------------------------------------
// v = Wv @ x_b[kk] + bv  -> g_v[kk][b][c][n]   (32 output rows per block.y)
// ---------------------------------------------------------------------------
__global__ void proj_v_kernel(const float* __restrict__ xball,
                              const float* __restrict__ W,
                              const float* __restrict__ bias) {
    __shared__ float Ws[C_ * 32];  // [c][orel]
    int tid = threadIdx.x;
    int z = blockIdx.z;              // kk*B + b
    int cbase = blockIdx.y * 32;
    for (int idx = tid; idx < 32 * C_; idx += 128) {
        int orel = idx >> 8, c = idx & 255;
        Ws[c * 32 + orel] = W[(size_t)(cbase + orel) * C_ + c];
    }
    __syncthreads();
    int n = blockIdx.x * 128 + tid;
    const float* xb = xball + (size_t)z * C_ * N_;
    float acc[32];
#pragma unroll
    for (int o = 0; o < 32; o++) acc[o] = bias[cbase + o];
    for (int c = 0; c < C_; c++) {
        float xv = xb[c * N_ + n];
#pragma unroll
        for (int o = 0; o < 32; o++) acc[o] = fmaf(Ws[c * 32 + o], xv, acc[o]);
    }
    float* out = g_v + ((size_t)z * C_ + cbase) * N_;
#pragma unroll
    for (int o = 0; o < 32; o++) out[(size_t)o * N_ + n] = acc[o];
}

// ---------------------------------------------------------------------------
// den[kk][b][i] = sum_j exp(q_i . k_j)
// ---------------------------------------------------------------------------
__global__ void denom_kernel() {
    __shared__ float Ks[C8_ * 128];
    int kk = blockIdx.z, b = blockIdx.y;
    int tid = threadIdx.x;
    int i = blockIdx.x * 128 + tid;
    const float* qp = g_q + ((size_t)(kk * B_ + b) * N_ + i) * C8_;
    float q[C8_];
#pragma unroll
    for (int o = 0; o < C8_; o += 4) {
        float4 v4 = *(const float4*)(qp + o);
        q[o] = v4.x; q[o + 1] = v4.y; q[o + 2] = v4.z; q[o + 3] = v4.w;
    }
    const float* kp = g_k + (size_t)b * C8_ * N_;
    float den = 0.f;
    for (int jt = 0; jt < N_; jt += 128) {
        __syncthreads();
        for (int idx = tid; idx < C8_ * 128; idx += 128) {
            int o = idx >> 7, j = idx & 127;
            Ks[idx] = kp[(size_t)o * N_ + jt + j];
        }
        __syncthreads();
#pragma unroll 4
        for (int j = 0; j < 128; j++) {
            float s = 0.f;
#pragma unroll
            for (int o = 0; o < C8_; o++) s = fmaf(q[o], Ks[o * 128 + j], s);
            den += __expf(s);
        }
    }
    g_den[(size_t)(kk * B_ + b) * N_ + i] = den;
}

// ---------------------------------------------------------------------------
// AV: g_acc[b][c][i] = sum_kk sum_j softmax(e)_{i,j} * v[kk][b][c][j]
// Block tile: TC=128 channels x TI=64 queries; thread micro-tile 8c x 4i.
// ---------------------------------------------------------------------------
__global__ void av_kernel() {
    extern __shared__ float sm[];
    float* Qs = sm;                    // TI x 33
    float* Ks = Qs + TI * 33;          // 32 x 65
    float* Ds = Ks + 32 * 65;          // TI
    float* Ps = Ds + TI;               // TI x 65
    float* Vs = Ps + TI * 65;          // TC x 65

    int tid = threadIdx.x;
    int b = blockIdx.z;
    int cbase = blockIdx.y * TC;
    int itile = blockIdx.x * TI;
    int tx = tid & 15;   // i direction
    int ty = tid >> 4;   // c direction

    float acc[8][4];
#pragma unroll
    for (int cc = 0; cc < 8; cc++)
#pragma unroll
        for (int ii = 0; ii < 4; ii++) acc[cc][ii] = 0.f;

    const float* kp = g_k + (size_t)b * C8_ * N_;

    for (int kk = 0; kk < K_; kk++) {
        size_t zb = (size_t)(kk * B_ + b);
        __syncthreads();
        const float* qp = g_q + (zb * N_ + itile) * C8_;
        for (int idx = tid; idx < TI * C8_; idx += 256) {
            int i = idx >> 5, o = idx & 31;
            Qs[i * 33 + o] = qp[idx];
        }
        if (tid < TI) Ds[tid] = 1.0f / g_den[zb * N_ + itile + tid];
        const float* vp = g_v + (zb * C_ + cbase) * N_;

        for (int jt = 0; jt < N_; jt += TJ) {
            __syncthreads();
#pragma unroll
            for (int r = 0; r < 8; r++) {
                int idx = tid + 256 * r;
                int o = idx >> 6, j = idx & 63;
                Ks[o * 65 + j] = kp[(size_t)o * N_ + jt + j];
            }
#pragma unroll
            for (int r = 0; r < 32; r++) {
                int idx = tid + 256 * r;
                int c = idx >> 6, j = idx & 63;
                Vs[c * 65 + j] = vp[(size_t)c * N_ + jt + j];
            }
            __syncthreads();
            // scores + exp -> Ps
            {
                int jloc = tid & 63;
                int igrp = tid >> 6;
#pragma unroll
                for (int r = 0; r < 16; r++) {
                    int i = igrp * 16 + r;
                    float s = 0.f;
#pragma unroll
                    for (int o = 0; o < C8_; o++)
                        s = fmaf(Qs[i * 33 + o], Ks[o * 65 + jloc], s);
                    Ps[i * 65 + jloc] = __expf(s) * Ds[i];
                }
            }
            __syncthreads();
            // main rank-TJ update
#pragma unroll 2
            for (int jj = 0; jj < TJ; jj++) {
                float pr[4], vr[8];
#pragma unroll
                for (int ii = 0; ii < 4; ii++) pr[ii] = Ps[(tx + 16 * ii) * 65 + jj];
#pragma unroll
                for (int cc = 0; cc < 8; cc++) vr[cc] = Vs[(ty + 16 * cc) * 65 + jj];
#pragma unroll
                for (int cc = 0; cc < 8; cc++)
#pragma unroll
                    for (int ii = 0; ii < 4; ii++)
                        acc[cc][ii] = fmaf(vr[cc], pr[ii], acc[cc][ii]);
            }
        }
    }

#pragma unroll
    for (int cc = 0; cc < 8; cc++) {
        int c = cbase + ty + 16 * cc;
#pragma unroll
        for (int ii = 0; ii < 4; ii++) {
            int n = itile + tx + 16 * ii;
            g_acc[((size_t)b * C_ + c) * N_ + n] = acc[cc][ii];
        }
    }
}

// ---------------------------------------------------------------------------
// final: out[b][o][n] = bf[o] + sum_c Wf[o][c]*gamma*acc + Wf[o][C+c]*xf
// ---------------------------------------------------------------------------
__global__ void final_kernel(const float* __restrict__ xf,
                             const float* __restrict__ Wf,
                             const float* __restrict__ bf,
                             const float* __restrict__ gptr,
                             float* __restrict__ out) {
    __shared__ float Ws[16 * 512];
    int tid = threadIdx.x;
    int b = blockIdx.z;
    int obase = blockIdx.y * 16;
    for (int idx = tid; idx < 16 * 512; idx += 128)
        Ws[idx] = Wf[(size_t)obase * 512 + idx];
    __syncthreads();
    int n = blockIdx.x * 128 + tid;
    float gamma = gptr[0];
    const float* xb = xf + (size_t)b * C_ * N_;
    const float* ab = g_acc + (size_t)b * C_ * N_;
    float acc[16];
#pragma unroll
    for (int o = 0; o < 16; o++) acc[o] = bf[obase + o];
    for (int c = 0; c < C_; c++) {
        float av = ab[c * N_ + n] * gamma;
        float xv = xb[c * N_ + n];
#pragma unroll
        for (int o = 0; o < 16; o++) {
            acc[o] = fmaf(Ws[o * 512 + c], av, acc[o]);
            acc[o] = fmaf(Ws[o * 512 + 256 + c], xv, acc[o]);
        }
    }
#pragma unroll
    for (int o = 0; o < 16; o++)
        out[((size_t)b * C_ + obase + o) * N_ + n] = acc[o];
}

// ---------------------------------------------------------------------------
extern "C" void kernel_launch(void* const* d_in, const int* in_sizes, int n_in,
                              void* d_out, int out_size) {
    const float* x_f = (const float*)d_in[0];
    const float* x_b = (const float*)d_in[1];
    const float* Wq  = (const float*)d_in[2];
    const float* bq  = (const float*)d_in[3];
    const float* Wk  = (const float*)d_in[4];
    const float* bk  = (const float*)d_in[5];
    const float* Wv  = (const float*)d_in[6];
    const float* bv  = (const float*)d_in[7];
    const float* Wf  = (const float*)d_in[8];
    const float* bf  = (const float*)d_in[9];
    const float* gm  = (const float*)d_in[10];
    float* out = (float*)d_out;

    const int AV_SMEM = (TI * 33 + 32 * 65 + TI + TI * 65 + TC * 65) * (int)sizeof(float);
    cudaFuncSetAttribute(av_kernel, cudaFuncAttributeMaxDynamicSharedMemorySize, AV_SMEM);

    proj_k_kernel<<<dim3(N_ / 128, B_), 128>>>(x_f, Wk, bk);
    proj_q_kernel<<<dim3(N_ / 128, B_, K_), 128>>>(x_b, Wq, bq);
    proj_v_kernel<<<dim3(N_ / 128, C_ / 32, K_ * B_), 128>>>(x_b, Wv, bv);
    denom_kernel<<<dim3(N_ / 128, B_, K_), 128>>>();
    av_kernel<<<dim3(N_ / TI, C_ / TC, B_), 256, AV_SMEM>>>();
    final_kernel<<<dim3(N_ / 128, C_ / 16, B_), 128>>>(x_f, Wf, bf, gm, out);
}

// round 5
// speedup vs baseline: 3.6397x; 3.6397x over previous
#include <cuda_runtime.h>
#include <cuda_bf16.h>
#include <cstdint>
#include <math.h>

constexpr int B_  = 4;
constexpr int C_  = 256;
constexpr int C8_ = 32;
constexpr int N_  = 4096;
constexpr int K_  = 3;

constexpr int TI = 128;   // queries per CTA
constexpr int TJ = 64;    // keys per j-step

// ---- scratch (device globals; no allocation allowed) ----------------------
__device__ __nv_bfloat16 g_q[(size_t)K_ * B_ * N_ * C8_];   // [kk*B+b][n][o]
__device__ __nv_bfloat16 g_k[(size_t)B_ * N_ * C8_];        // [b][n][o]
__device__ __nv_bfloat16 g_v[(size_t)K_ * B_ * C_ * N_];    // [kk*B+b][c][n]
__device__ float         g_acc[(size_t)B_ * C_ * N_];       // [b][c][n]

// ---- helpers --------------------------------------------------------------
__device__ __forceinline__ uint32_t smem_u32(const void* p) {
    uint32_t a;
    asm("{ .reg .u64 t; cvta.to.shared.u64 t, %1; cvt.u32.u64 %0, t; }" : "=r"(a) : "l"(p));
    return a;
}
__device__ __forceinline__ void ldsm4(uint32_t* r, uint32_t addr) {
    asm volatile("ldmatrix.sync.aligned.m8n8.x4.shared.b16 {%0,%1,%2,%3}, [%4];"
                 : "=r"(r[0]), "=r"(r[1]), "=r"(r[2]), "=r"(r[3]) : "r"(addr));
}
__device__ __forceinline__ void mma16816(float* d, const uint32_t* a, uint32_t b0, uint32_t b1) {
    asm volatile("mma.sync.aligned.m16n8k16.row.col.f32.bf16.bf16.f32 "
                 "{%0,%1,%2,%3}, {%4,%5,%6,%7}, {%8,%9}, {%0,%1,%2,%3};"
                 : "+f"(d[0]), "+f"(d[1]), "+f"(d[2]), "+f"(d[3])
                 : "r"(a[0]), "r"(a[1]), "r"(a[2]), "r"(a[3]), "r"(b0), "r"(b1));
}
__device__ __forceinline__ uint32_t packbf2(float x, float y) {
    __nv_bfloat162 h = __float22bfloat162_rn(make_float2(x, y));
    return *(uint32_t*)&h;
}

// ---- smem layout: padded row strides, conflict-free for ldmatrix ----------
constexpr int QROW = 80;    // 64B data + 16B pad
constexpr int KROW = 80;
constexpr int VROW = 144;   // 128B data + 16B pad
constexpr int SM_Q = 0;                       // 128 * 80   = 10240
constexpr int SM_K = 10240;                   // 64  * 80   = 5120
constexpr int SM_V = 15360;                   // 256 * 144  = 36864
constexpr int SM_TOTAL = SM_V + 256 * VROW;   // 52224

// ---------------------------------------------------------------------------
__global__ void __launch_bounds__(256, 1) attn_kernel() {
    extern __shared__ char smem[];
    uint32_t sb = smem_u32(smem);
    int tid = threadIdx.x, wid = tid >> 5, lane = tid & 31;
    int b = blockIdx.y;
    int itile = blockIdx.x * TI;
    int wrow = wid * 16;

    // ldmatrix per-lane base addresses
    uint32_t qaddr = sb + SM_Q + (wrow + (lane & 15)) * QROW + ((lane >> 4) & 1) * 16;
    uint32_t kaddr = sb + SM_K + ((((lane >> 4) & 1) * 8 + (lane & 7))) * KROW + ((lane >> 3) & 1) * 16;
    uint32_t vaddr = sb + SM_V + ((((lane >> 4) & 1) * 8 + (lane & 7))) * VROW + ((lane >> 3) & 1) * 16;

    const __nv_bfloat16* kbase = g_k + (size_t)b * N_ * C8_;

    for (int kk = 0; kk < K_; kk++) {
        size_t zb = (size_t)kk * B_ + b;
        __syncthreads();
        // Q tile -> smem (128 rows x 64B)
        const __nv_bfloat16* qp = g_q + (zb * N_ + itile) * C8_;
        for (int t = tid; t < 512; t += 256) {
            int r = t >> 2, ch = t & 3;
            *(uint4*)(smem + SM_Q + r * QROW + ch * 16) = *(const uint4*)(qp + r * C8_ + ch * 8);
        }
        __syncthreads();
        uint32_t qa[2][4];
        ldsm4(qa[0], qaddr);
        ldsm4(qa[1], qaddr + 32);

        float Dn[32][4];
#pragma unroll
        for (int c = 0; c < 32; c++)
#pragma unroll
            for (int p = 0; p < 4; p++) Dn[c][p] = 0.f;
        float den0 = 0.f, den1 = 0.f;

        const __nv_bfloat16* vbase = g_v + zb * (size_t)C_ * N_;

        for (int jt = 0; jt < N_; jt += TJ) {
            __syncthreads();
            // K tile (64 rows x 64B)
            {
                int r = tid >> 2, ch = tid & 3;
                *(uint4*)(smem + SM_K + r * KROW + ch * 16) =
                    *(const uint4*)(kbase + (size_t)(jt + r) * C8_ + ch * 8);
            }
            // V tile (256 rows(c) x 128B(j))
            for (int t = tid; t < 2048; t += 256) {
                int c = t >> 3, ch = t & 7;
                *(uint4*)(smem + SM_V + c * VROW + ch * 16) =
                    *(const uint4*)(vbase + (size_t)c * N_ + jt + ch * 8);
            }
            __syncthreads();

            // ---- GEMM1: S[16 x 64] = Q . K^T ----
            float s[8][4];
#pragma unroll
            for (int t = 0; t < 8; t++)
#pragma unroll
                for (int p = 0; p < 4; p++) s[t][p] = 0.f;
#pragma unroll
            for (int kc = 0; kc < 2; kc++) {
#pragma unroll
                for (int tp = 0; tp < 4; tp++) {
                    uint32_t kb[4];
                    ldsm4(kb, kaddr + tp * 16 * KROW + kc * 32);
                    mma16816(s[2 * tp],     qa[kc], kb[0], kb[1]);
                    mma16816(s[2 * tp + 1], qa[kc], kb[2], kb[3]);
                }
            }
            // ---- exp + pack to bf16 A-fragments, accumulate denominator ----
            uint32_t pa[8], pb[8];
#pragma unroll
            for (int t = 0; t < 8; t++) {
                float e0 = __expf(s[t][0]), e1 = __expf(s[t][1]);
                float e2 = __expf(s[t][2]), e3 = __expf(s[t][3]);
                den0 += e0 + e1;
                den1 += e2 + e3;
                pa[t] = packbf2(e0, e1);
                pb[t] = packbf2(e2, e3);
            }
            // ---- GEMM2: D[16 x 256] += P . V^T ----
#pragma unroll
            for (int ctp = 0; ctp < 16; ctp++) {
#pragma unroll
                for (int tp = 0; tp < 4; tp++) {
                    uint32_t vb[4];
                    ldsm4(vb, vaddr + ctp * 16 * VROW + tp * 32);
                    uint32_t af[4] = {pa[2 * tp], pb[2 * tp], pa[2 * tp + 1], pb[2 * tp + 1]};
                    mma16816(Dn[2 * ctp],     af, vb[0], vb[1]);
                    mma16816(Dn[2 * ctp + 1], af, vb[2], vb[3]);
                }
            }
        }

        // row denominators (rows are warp-private; reduce over the 4 lanes of a row)
        den0 += __shfl_xor_sync(0xffffffffu, den0, 1);
        den0 += __shfl_xor_sync(0xffffffffu, den0, 2);
        den1 += __shfl_xor_sync(0xffffffffu, den1, 1);
        den1 += __shfl_xor_sync(0xffffffffu, den1, 2);
        float inv0 = 1.f / den0, inv1 = 1.f / den1;

        // normalize + accumulate into g_acc[b][c][n]
        int n0 = itile + wrow + (lane >> 2);
        int cbase0 = 2 * (lane & 3);
        float* accb = g_acc + (size_t)b * C_ * N_;
#pragma unroll
        for (int ct = 0; ct < 32; ct++) {
            int c = 8 * ct + cbase0;
            float* p0 = accb + (size_t)c * N_ + n0;
            float* p1 = p0 + N_;
            float v0 = Dn[ct][0] * inv0, v1 = Dn[ct][1] * inv0;
            float v2 = Dn[ct][2] * inv1, v3 = Dn[ct][3] * inv1;
            if (kk == 0) {
                p0[0] = v0; p1[0] = v1; p0[8] = v2; p1[8] = v3;
            } else {
                p0[0] += v0; p1[0] += v1; p0[8] += v2; p1[8] += v3;
            }
        }
    }
}

// ---------------------------------------------------------------------------
// q projection -> g_q bf16 [zb][n][32]
__global__ void proj_q_kernel(const float* __restrict__ xball,
                              const float* __restrict__ W,
                              const float* __restrict__ bias) {
    __shared__ float Ws[C_ * C8_];
    int tid = threadIdx.x;
    for (int idx = tid; idx < C_ * C8_; idx += 128) {
        int o = idx >> 8, c = idx & 255;
        Ws[c * C8_ + o] = W[idx];
    }
    __syncthreads();
    int z = blockIdx.z * B_ + blockIdx.y;
    int n = blockIdx.x * 128 + tid;
    const float* xb = xball + (size_t)z * C_ * N_;
    float acc[C8_];
#pragma unroll
    for (int o = 0; o < C8_; o++) acc[o] = bias[o];
    for (int c = 0; c < C_; c++) {
        float xv = xb[c * N_ + n];
#pragma unroll
        for (int o = 0; o < C8_; o++) acc[o] = fmaf(Ws[c * C8_ + o], xv, acc[o]);
    }
    __nv_bfloat162* op = (__nv_bfloat162*)(g_q + ((size_t)z * N_ + n) * C8_);
#pragma unroll
    for (int o = 0; o < C8_; o += 2)
        op[o >> 1] = __float22bfloat162_rn(make_float2(acc[o], acc[o + 1]));
}

// k projection -> g_k bf16 [b][n][32]
__global__ void proj_k_kernel(const float* __restrict__ x,
                              const float* __restrict__ W,
                              const float* __restrict__ bias) {
    __shared__ float Ws[C_ * C8_];
    int tid = threadIdx.x;
    for (int idx = tid; idx < C_ * C8_; idx += 128) {
        int o = idx >> 8, c = idx & 255;
        Ws[c * C8_ + o] = W[idx];
    }
    __syncthreads();
    int b = blockIdx.y;
    int n = blockIdx.x * 128 + tid;
    const float* xb = x + (size_t)b * C_ * N_;
    float acc[C8_];
#pragma unroll
    for (int o = 0; o < C8_; o++) acc[o] = bias[o];
    for (int c = 0; c < C_; c++) {
        float xv = xb[c * N_ + n];
#pragma unroll
        for (int o = 0; o < C8_; o++) acc[o] = fmaf(Ws[c * C8_ + o], xv, acc[o]);
    }
    __nv_bfloat162* op = (__nv_bfloat162*)(g_k + ((size_t)b * N_ + n) * C8_);
#pragma unroll
    for (int o = 0; o < C8_; o += 2)
        op[o >> 1] = __float22bfloat162_rn(make_float2(acc[o], acc[o + 1]));
}

// v projection -> g_v bf16 [zb][c][n]
__global__ void proj_v_kernel(const float* __restrict__ xball,
                              const float* __restrict__ W,
                              const float* __restrict__ bias) {
    __shared__ float Ws[C_ * 32];
    int tid = threadIdx.x;
    int z = blockIdx.z;
    int cbase = blockIdx.y * 32;
    for (int idx = tid; idx < 32 * C_; idx += 128) {
        int orel = idx >> 8, c = idx & 255;
        Ws[c * 32 + orel] = W[(size_t)(cbase + orel) * C_ + c];
    }
    __syncthreads();
    int n = blockIdx.x * 128 + tid;
    const float* xb = xball + (size_t)z * C_ * N_;
    float acc[32];
#pragma unroll
    for (int o = 0; o < 32; o++) acc[o] = bias[cbase + o];
    for (int c = 0; c < C_; c++) {
        float xv = xb[c * N_ + n];
#pragma unroll
        for (int o = 0; o < 32; o++) acc[o] = fmaf(Ws[c * 32 + o], xv, acc[o]);
    }
    __nv_bfloat16* out = g_v + ((size_t)z * C_ + cbase) * N_;
#pragma unroll
    for (int o = 0; o < 32; o++) out[(size_t)o * N_ + n] = __float2bfloat16(acc[o]);
}

// final: out[b][o][n] = bf[o] + sum_c Wf[o][c]*gamma*acc + Wf[o][C+c]*xf
__global__ void final_kernel(const float* __restrict__ xf,
                             const float* __restrict__ Wf,
                             const float* __restrict__ bf,
                             const float* __restrict__ gptr,
                             float* __restrict__ out) {
    __shared__ float Ws[16 * 512];
    int tid = threadIdx.x;
    int b = blockIdx.z;
    int obase = blockIdx.y * 16;
    for (int idx = tid; idx < 16 * 512; idx += 128)
        Ws[idx] = Wf[(size_t)obase * 512 + idx];
    __syncthreads();
    int n = blockIdx.x * 128 + tid;
    float gamma = gptr[0];
    const float* xb = xf + (size_t)b * C_ * N_;
    const float* ab = g_acc + (size_t)b * C_ * N_;
    float acc[16];
#pragma unroll
    for (int o = 0; o < 16; o++) acc[o] = bf[obase + o];
    for (int c = 0; c < C_; c++) {
        float av = ab[c * N_ + n] * gamma;
        float xv = xb[c * N_ + n];
#pragma unroll
        for (int o = 0; o < 16; o++) {
            acc[o] = fmaf(Ws[o * 512 + c], av, acc[o]);
            acc[o] = fmaf(Ws[o * 512 + 256 + c], xv, acc[o]);
        }
    }
#pragma unroll
    for (int o = 0; o < 16; o++)
        out[((size_t)b * C_ + obase + o) * N_ + n] = acc[o];
}

// ---------------------------------------------------------------------------
extern "C" void kernel_launch(void* const* d_in, const int* in_sizes, int n_in,
                              void* d_out, int out_size) {
    const float* x_f = (const float*)d_in[0];
    const float* x_b = (const float*)d_in[1];
    const float* Wq  = (const float*)d_in[2];
    const float* bq  = (const float*)d_in[3];
    const float* Wk  = (const float*)d_in[4];
    const float* bk  = (const float*)d_in[5];
    const float* Wv  = (const float*)d_in[6];
    const float* bv  = (const float*)d_in[7];
    const float* Wf  = (const float*)d_in[8];
    const float* bf  = (const float*)d_in[9];
    const float* gm  = (const float*)d_in[10];
    float* out = (float*)d_out;

    cudaFuncSetAttribute(attn_kernel, cudaFuncAttributeMaxDynamicSharedMemorySize, SM_TOTAL);

    proj_k_kernel<<<dim3(N_ / 128, B_), 128>>>(x_f, Wk, bk);
    proj_q_kernel<<<dim3(N_ / 128, B_, K_), 128>>>(x_b, Wq, bq);
    proj_v_kernel<<<dim3(N_ / 128, C_ / 32, K_ * B_), 128>>>(x_b, Wv, bv);
    attn_kernel<<<dim3(N_ / TI, B_), 256, SM_TOTAL>>>();
    final_kernel<<<dim3(N_ / 128, C_ / 16, B_), 128>>>(x_f, Wf, bf, gm, out);
}

// round 6
// speedup vs baseline: 4.0426x; 1.1107x over previous
#include <cuda_runtime.h>
#include <cuda_bf16.h>
#include <cstdint>
#include <math.h>

constexpr int B_  = 4;
constexpr int C_  = 256;
constexpr int C8_ = 32;
constexpr int N_  = 4096;
constexpr int K_  = 3;

constexpr int TI = 128;   // queries per CTA
constexpr int TJ = 64;    // keys per j-step
constexpr int TC = 128;   // channels per CTA (split across blockIdx.y)

// ---- scratch (device globals; no allocation allowed) ----------------------
__device__ __nv_bfloat16 g_q[(size_t)K_ * B_ * N_ * C8_];   // [kk*B+b][n][o]
__device__ __nv_bfloat16 g_k[(size_t)B_ * N_ * C8_];        // [b][n][o]
__device__ __nv_bfloat16 g_v[(size_t)K_ * B_ * C_ * N_];    // [kk*B+b][c][n]
__device__ float         g_acc[(size_t)B_ * C_ * N_];       // [b][c][n]

// ---- helpers --------------------------------------------------------------
__device__ __forceinline__ uint32_t smem_u32(const void* p) {
    uint32_t a;
    asm("{ .reg .u64 t; cvta.to.shared.u64 t, %1; cvt.u32.u64 %0, t; }" : "=r"(a) : "l"(p));
    return a;
}
__device__ __forceinline__ void ldsm4(uint32_t* r, uint32_t addr) {
    asm volatile("ldmatrix.sync.aligned.m8n8.x4.shared.b16 {%0,%1,%2,%3}, [%4];"
                 : "=r"(r[0]), "=r"(r[1]), "=r"(r[2]), "=r"(r[3]) : "r"(addr));
}
__device__ __forceinline__ void mma16816(float* d, const uint32_t* a, uint32_t b0, uint32_t b1) {
    asm volatile("mma.sync.aligned.m16n8k16.row.col.f32.bf16.bf16.f32 "
                 "{%0,%1,%2,%3}, {%4,%5,%6,%7}, {%8,%9}, {%0,%1,%2,%3};"
                 : "+f"(d[0]), "+f"(d[1]), "+f"(d[2]), "+f"(d[3])
                 : "r"(a[0]), "r"(a[1]), "r"(a[2]), "r"(a[3]), "r"(b0), "r"(b1));
}
__device__ __forceinline__ uint32_t packbf2(float x, float y) {
    __nv_bfloat162 h = __float22bfloat162_rn(make_float2(x, y));
    return *(uint32_t*)&h;
}

// ---- smem layout: padded row strides, conflict-free for ldmatrix ----------
constexpr int QROW = 80;    // 64B data + 16B pad
constexpr int KROW = 80;
constexpr int VROW = 144;   // 128B data + 16B pad
constexpr int SM_Q = 0;                       // 128 * 80  = 10240
constexpr int SM_K = 10240;                   // 64  * 80  = 5120
constexpr int SM_V = 15360;                   // 128 * 144 = 18432
constexpr int SM_TOTAL = SM_V + TC * VROW;    // 33792

// ---------------------------------------------------------------------------
__global__ void __launch_bounds__(256, 2) attn_kernel() {
    extern __shared__ char smem[];
    uint32_t sb = smem_u32(smem);
    int tid = threadIdx.x, wid = tid >> 5, lane = tid & 31;
    int b = blockIdx.z;
    int cbase = blockIdx.y * TC;
    int itile = blockIdx.x * TI;
    int wrow = wid * 16;

    // ldmatrix per-lane base addresses
    uint32_t qaddr = sb + SM_Q + (wrow + (lane & 15)) * QROW + ((lane >> 4) & 1) * 16;
    uint32_t kaddr = sb + SM_K + ((((lane >> 4) & 1) * 8 + (lane & 7))) * KROW + ((lane >> 3) & 1) * 16;
    uint32_t vaddr = sb + SM_V + ((((lane >> 4) & 1) * 8 + (lane & 7))) * VROW + ((lane >> 3) & 1) * 16;

    const __nv_bfloat16* kbase = g_k + (size_t)b * N_ * C8_;

    for (int kk = 0; kk < K_; kk++) {
        size_t zb = (size_t)kk * B_ + b;
        __syncthreads();
        // Q tile -> smem (128 rows x 64B)
        const __nv_bfloat16* qp = g_q + (zb * N_ + itile) * C8_;
        for (int t = tid; t < 512; t += 256) {
            int r = t >> 2, ch = t & 3;
            *(uint4*)(smem + SM_Q + r * QROW + ch * 16) = *(const uint4*)(qp + r * C8_ + ch * 8);
        }
        __syncthreads();
        uint32_t qa[2][4];
        ldsm4(qa[0], qaddr);
        ldsm4(qa[1], qaddr + 32);

        float Dn[16][4];
#pragma unroll
        for (int c = 0; c < 16; c++)
#pragma unroll
            for (int p = 0; p < 4; p++) Dn[c][p] = 0.f;
        float den0 = 0.f, den1 = 0.f;

        const __nv_bfloat16* vbase = g_v + (zb * C_ + cbase) * (size_t)N_;

        for (int jt = 0; jt < N_; jt += TJ) {
            __syncthreads();
            // K tile (64 rows x 64B)
            {
                int r = tid >> 2, ch = tid & 3;
                *(uint4*)(smem + SM_K + r * KROW + ch * 16) =
                    *(const uint4*)(kbase + (size_t)(jt + r) * C8_ + ch * 8);
            }
            // V tile (TC rows(c) x 128B(j))
            for (int t = tid; t < TC * 8; t += 256) {
                int c = t >> 3, ch = t & 7;
                *(uint4*)(smem + SM_V + c * VROW + ch * 16) =
                    *(const uint4*)(vbase + (size_t)c * N_ + jt + ch * 8);
            }
            __syncthreads();

            // ---- GEMM1: S[16 x 64] = Q . K^T ----
            float s[8][4];
#pragma unroll
            for (int t = 0; t < 8; t++)
#pragma unroll
                for (int p = 0; p < 4; p++) s[t][p] = 0.f;
#pragma unroll
            for (int kc = 0; kc < 2; kc++) {
#pragma unroll
                for (int tp = 0; tp < 4; tp++) {
                    uint32_t kb[4];
                    ldsm4(kb, kaddr + tp * 16 * KROW + kc * 32);
                    mma16816(s[2 * tp],     qa[kc], kb[0], kb[1]);
                    mma16816(s[2 * tp + 1], qa[kc], kb[2], kb[3]);
                }
            }
            // ---- exp + pack to bf16 A-fragments, accumulate denominator ----
            uint32_t pa[8], pb[8];
#pragma unroll
            for (int t = 0; t < 8; t++) {
                float e0 = __expf(s[t][0]), e1 = __expf(s[t][1]);
                float e2 = __expf(s[t][2]), e3 = __expf(s[t][3]);
                den0 += e0 + e1;
                den1 += e2 + e3;
                pa[t] = packbf2(e0, e1);
                pb[t] = packbf2(e2, e3);
            }
            // ---- GEMM2: D[16 x TC] += P . V^T ----
#pragma unroll
            for (int ctp = 0; ctp < TC / 16; ctp++) {
#pragma unroll
                for (int tp = 0; tp < 4; tp++) {
                    uint32_t vb[4];
                    ldsm4(vb, vaddr + ctp * 16 * VROW + tp * 32);
                    uint32_t af[4] = {pa[2 * tp], pb[2 * tp], pa[2 * tp + 1], pb[2 * tp + 1]};
                    mma16816(Dn[2 * ctp],     af, vb[0], vb[1]);
                    mma16816(Dn[2 * ctp + 1], af, vb[2], vb[3]);
                }
            }
        }

        // row denominators (rows are warp-private; reduce over the 4 lanes of a row)
        den0 += __shfl_xor_sync(0xffffffffu, den0, 1);
        den0 += __shfl_xor_sync(0xffffffffu, den0, 2);
        den1 += __shfl_xor_sync(0xffffffffu, den1, 1);
        den1 += __shfl_xor_sync(0xffffffffu, den1, 2);
        float inv0 = 1.f / den0, inv1 = 1.f / den1;

        // normalize + accumulate into g_acc[b][c][n]
        int n0 = itile + wrow + (lane >> 2);
        int cbase0 = cbase + 2 * (lane & 3);
        float* accb = g_acc + (size_t)b * C_ * N_;
#pragma unroll
        for (int ct = 0; ct < 16; ct++) {
            int c = 8 * ct + cbase0;
            float* p0 = accb + (size_t)c * N_ + n0;
            float* p1 = p0 + N_;
            float v0 = Dn[ct][0] * inv0, v1 = Dn[ct][1] * inv0;
            float v2 = Dn[ct][2] * inv1, v3 = Dn[ct][3] * inv1;
            if (kk == 0) {
                p0[0] = v0; p1[0] = v1; p0[8] = v2; p1[8] = v3;
            } else {
                p0[0] += v0; p1[0] += v1; p0[8] += v2; p1[8] += v3;
            }
        }
    }
}

// ---------------------------------------------------------------------------
// q projection -> g_q bf16 [zb][n][32]
__global__ void proj_q_kernel(const float* __restrict__ xball,
                              const float* __restrict__ W,
                              const float* __restrict__ bias) {
    __shared__ float Ws[C_ * C8_];
    int tid = threadIdx.x;
    for (int idx = tid; idx < C_ * C8_; idx += 128) {
        int o = idx >> 8, c = idx & 255;
        Ws[c * C8_ + o] = W[idx];
    }
    __syncthreads();
    int z = blockIdx.z * B_ + blockIdx.y;
    int n = blockIdx.x * 128 + tid;
    const float* xb = xball + (size_t)z * C_ * N_;
    float acc[C8_];
#pragma unroll
    for (int o = 0; o < C8_; o++) acc[o] = bias[o];
    for (int c = 0; c < C_; c++) {
        float xv = xb[c * N_ + n];
#pragma unroll
        for (int o = 0; o < C8_; o++) acc[o] = fmaf(Ws[c * C8_ + o], xv, acc[o]);
    }
    __nv_bfloat162* op = (__nv_bfloat162*)(g_q + ((size_t)z * N_ + n) * C8_);
#pragma unroll
    for (int o = 0; o < C8_; o += 2)
        op[o >> 1] = __float22bfloat162_rn(make_float2(acc[o], acc[o + 1]));
}

// k projection -> g_k bf16 [b][n][32]
__global__ void proj_k_kernel(const float* __restrict__ x,
                              const float* __restrict__ W,
                              const float* __restrict__ bias) {
    __shared__ float Ws[C_ * C8_];
    int tid = threadIdx.x;
    for (int idx = tid; idx < C_ * C8_; idx += 128) {
        int o = idx >> 8, c = idx & 255;
        Ws[c * C8_ + o] = W[idx];
    }
    __syncthreads();
    int b = blockIdx.y;
    int n = blockIdx.x * 128 + tid;
    const float* xb = x + (size_t)b * C_ * N_;
    float acc[C8_];
#pragma unroll
    for (int o = 0; o < C8_; o++) acc[o] = bias[o];
    for (int c = 0; c < C_; c++) {
        float xv = xb[c * N_ + n];
#pragma unroll
        for (int o = 0; o < C8_; o++) acc[o] = fmaf(Ws[c * C8_ + o], xv, acc[o]);
    }
    __nv_bfloat162* op = (__nv_bfloat162*)(g_k + ((size_t)b * N_ + n) * C8_);
#pragma unroll
    for (int o = 0; o < C8_; o += 2)
        op[o >> 1] = __float22bfloat162_rn(make_float2(acc[o], acc[o + 1]));
}

// v projection -> g_v bf16 [zb][c][n]; each thread handles 2 n-values
__global__ void proj_v_kernel(const float* __restrict__ xball,
                              const float* __restrict__ W,
                              const float* __restrict__ bias) {
    __shared__ float Ws[C_ * 32];
    int tid = threadIdx.x;
    int z = blockIdx.z;
    int cbase = blockIdx.y * 32;
    for (int idx = tid; idx < 32 * C_; idx += 128) {
        int orel = idx >> 8, c = idx & 255;
        Ws[c * 32 + orel] = W[(size_t)(cbase + orel) * C_ + c];
    }
    __syncthreads();
    int n = blockIdx.x * 256 + tid;   // n and n+128
    const float* xb = xball + (size_t)z * C_ * N_;
    float acc0[32], acc1[32];
#pragma unroll
    for (int o = 0; o < 32; o++) { acc0[o] = bias[cbase + o]; acc1[o] = acc0[o]; }
    for (int c = 0; c < C_; c++) {
        float xv0 = xb[c * N_ + n];
        float xv1 = xb[c * N_ + n + 128];
#pragma unroll
        for (int o = 0; o < 32; o++) {
            float w = Ws[c * 32 + o];
            acc0[o] = fmaf(w, xv0, acc0[o]);
            acc1[o] = fmaf(w, xv1, acc1[o]);
        }
    }
    __nv_bfloat16* out = g_v + ((size_t)z * C_ + cbase) * N_;
#pragma unroll
    for (int o = 0; o < 32; o++) {
        out[(size_t)o * N_ + n]       = __float2bfloat16(acc0[o]);
        out[(size_t)o * N_ + n + 128] = __float2bfloat16(acc1[o]);
    }
}

// final: out[b][o][n] = bf[o] + sum_c Wf[o][c]*gamma*acc + Wf[o][C+c]*xf
// each thread handles 2 n-values
__global__ void final_kernel(const float* __restrict__ xf,
                             const float* __restrict__ Wf,
                             const float* __restrict__ bf,
                             const float* __restrict__ gptr,
                             float* __restrict__ out) {
    __shared__ float Ws[16 * 512];
    int tid = threadIdx.x;
    int b = blockIdx.z;
    int obase = blockIdx.y * 16;
    for (int idx = tid; idx < 16 * 512; idx += 128)
        Ws[idx] = Wf[(size_t)obase * 512 + idx];
    __syncthreads();
    int n = blockIdx.x * 256 + tid;   // n and n+128
    float gamma = gptr[0];
    const float* xb = xf + (size_t)b * C_ * N_;
    const float* ab = g_acc + (size_t)b * C_ * N_;
    float acc0[16], acc1[16];
#pragma unroll
    for (int o = 0; o < 16; o++) { acc0[o] = bf[obase + o]; acc1[o] = acc0[o]; }
    for (int c = 0; c < C_; c++) {
        float av0 = ab[c * N_ + n] * gamma;
        float av1 = ab[c * N_ + n + 128] * gamma;
        float xv0 = xb[c * N_ + n];
        float xv1 = xb[c * N_ + n + 128];
#pragma unroll
        for (int o = 0; o < 16; o++) {
            float wa = Ws[o * 512 + c];
            float wx = Ws[o * 512 + 256 + c];
            acc0[o] = fmaf(wa, av0, acc0[o]);
            acc0[o] = fmaf(wx, xv0, acc0[o]);
            acc1[o] = fmaf(wa, av1, acc1[o]);
            acc1[o] = fmaf(wx, xv1, acc1[o]);
        }
    }
#pragma unroll
    for (int o = 0; o < 16; o++) {
        float* p = out + ((size_t)b * C_ + obase + o) * N_ + n;
        p[0] = acc0[o];
        p[128] = acc1[o];
    }
}

// ---------------------------------------------------------------------------
extern "C" void kernel_launch(void* const* d_in, const int* in_sizes, int n_in,
                              void* d_out, int out_size) {
    const float* x_f = (const float*)d_in[0];
    const float* x_b = (const float*)d_in[1];
    const float* Wq  = (const float*)d_in[2];
    const float* bq  = (const float*)d_in[3];
    const float* Wk  = (const float*)d_in[4];
    const float* bk  = (const float*)d_in[5];
    const float* Wv  = (const float*)d_in[6];
    const float* bv  = (const float*)d_in[7];
    const float* Wf  = (const float*)d_in[8];
    const float* bf  = (const float*)d_in[9];
    const float* gm  = (const float*)d_in[10];
    float* out = (float*)d_out;

    cudaFuncSetAttribute(attn_kernel, cudaFuncAttributeMaxDynamicSharedMemorySize, SM_TOTAL);

    proj_k_kernel<<<dim3(N_ / 128, B_), 128>>>(x_f, Wk, bk);
    proj_q_kernel<<<dim3(N_ / 128, B_, K_), 128>>>(x_b, Wq, bq);
    proj_v_kernel<<<dim3(N_ / 256, C_ / 32, K_ * B_), 128>>>(x_b, Wv, bv);
    attn_kernel<<<dim3(N_ / TI, C_ / TC, B_), 256, SM_TOTAL>>>();
    final_kernel<<<dim3(N_ / 256, C_ / 16, B_), 128>>>(x_f, Wf, bf, gm, out);
}

// round 7
// speedup vs baseline: 4.5946x; 1.1365x over previous
#include <cuda_runtime.h>
#include <cuda_bf16.h>
#include <cstdint>
#include <math.h>

constexpr int B_  = 4;
constexpr int C_  = 256;
constexpr int C8_ = 32;
constexpr int N_  = 4096;
constexpr int K_  = 3;

constexpr int TI = 128;   // queries per CTA
constexpr int TJ = 64;    // keys per j-step
constexpr int TC = 128;   // channels per CTA (split across blockIdx.y)
constexpr int NSTEP = N_ / TJ;

// ---- scratch (device globals; no allocation allowed) ----------------------
__device__ __nv_bfloat16 g_q[(size_t)K_ * B_ * N_ * C8_];   // [kk*B+b][n][o]
__device__ __nv_bfloat16 g_k[(size_t)B_ * N_ * C8_];        // [b][n][o]
__device__ __nv_bfloat16 g_v[(size_t)K_ * B_ * C_ * N_];    // [kk*B+b][c][n]
__device__ float         g_acc[(size_t)B_ * C_ * N_];       // [b][c][n]

// ---- helpers --------------------------------------------------------------
__device__ __forceinline__ uint32_t smem_u32(const void* p) {
    uint32_t a;
    asm("{ .reg .u64 t; cvta.to.shared.u64 t, %1; cvt.u32.u64 %0, t; }" : "=r"(a) : "l"(p));
    return a;
}
__device__ __forceinline__ void ldsm4(uint32_t* r, uint32_t addr) {
    asm volatile("ldmatrix.sync.aligned.m8n8.x4.shared.b16 {%0,%1,%2,%3}, [%4];"
                 : "=r"(r[0]), "=r"(r[1]), "=r"(r[2]), "=r"(r[3]) : "r"(addr));
}
__device__ __forceinline__ void mma16816(float* d, const uint32_t* a, uint32_t b0, uint32_t b1) {
    asm volatile("mma.sync.aligned.m16n8k16.row.col.f32.bf16.bf16.f32 "
                 "{%0,%1,%2,%3}, {%4,%5,%6,%7}, {%8,%9}, {%0,%1,%2,%3};"
                 : "+f"(d[0]), "+f"(d[1]), "+f"(d[2]), "+f"(d[3])
                 : "r"(a[0]), "r"(a[1]), "r"(a[2]), "r"(a[3]), "r"(b0), "r"(b1));
}
__device__ __forceinline__ uint32_t packbf2(float x, float y) {
    __nv_bfloat162 h = __float22bfloat162_rn(make_float2(x, y));
    return *(uint32_t*)&h;
}
__device__ __forceinline__ void cp16(uint32_t dst, const void* src) {
    asm volatile("cp.async.cg.shared.global [%0], [%1], 16;" :: "r"(dst), "l"(src));
}
#define CP_COMMIT() asm volatile("cp.async.commit_group;" ::: "memory")
#define CP_WAIT1()  asm volatile("cp.async.wait_group 1;" ::: "memory")

// ---- smem layout: padded row strides, conflict-free for ldmatrix ----------
constexpr int QROW = 80;    // 64B data + 16B pad
constexpr int KROW = 80;
constexpr int VROW = 144;   // 128B data + 16B pad
constexpr int SM_Q  = 0;                      // 128 * 80  = 10240
constexpr int SM_K0 = 10240;                  // 64  * 80  = 5120
constexpr int SM_V0 = SM_K0 + 64 * KROW;      // 128 * 144 = 18432
constexpr int BUFD  = 64 * KROW + TC * VROW;  // 23552
constexpr int SM_TOTAL = SM_K0 + 2 * BUFD;    // 57344

// ---------------------------------------------------------------------------
__global__ void __launch_bounds__(256, 2) attn_kernel() {
    extern __shared__ char smem[];
    uint32_t sb = smem_u32(smem);
    int tid = threadIdx.x, wid = tid >> 5, lane = tid & 31;
    int b = blockIdx.z;
    int cbase = blockIdx.y * TC;
    int itile = blockIdx.x * TI;
    int wrow = wid * 16;

    // ldmatrix per-lane base offsets (within a buffer)
    uint32_t qaddr = sb + SM_Q + (wrow + (lane & 15)) * QROW + ((lane >> 4) & 1) * 16;
    uint32_t koff = ((((lane >> 4) & 1) * 8 + (lane & 7))) * KROW + ((lane >> 3) & 1) * 16;
    uint32_t voff = 64 * KROW + ((((lane >> 4) & 1) * 8 + (lane & 7))) * VROW + ((lane >> 3) & 1) * 16;

    // cp.async per-thread destinations (within a buffer)
    uint32_t kdst = (tid >> 2) * KROW + (tid & 3) * 16;

    const __nv_bfloat16* kbase = g_k + (size_t)b * N_ * C8_;

    for (int kk = 0; kk < K_; kk++) {
        size_t zb = (size_t)kk * B_ + b;
        const __nv_bfloat16* vbase = g_v + (zb * C_ + cbase) * (size_t)N_;
        __syncthreads();
        // Q tile -> smem (128 rows x 64B)
        const __nv_bfloat16* qp = g_q + (zb * N_ + itile) * C8_;
        for (int t = tid; t < 512; t += 256) {
            int r = t >> 2, ch = t & 3;
            *(uint4*)(smem + SM_Q + r * QROW + ch * 16) = *(const uint4*)(qp + r * C8_ + ch * 8);
        }

        // prologue: async-load K,V tile 0 into buffer 0
        {
            uint32_t bufb = sb + SM_K0;
            cp16(bufb + kdst, kbase + (size_t)(tid >> 2) * C8_ + (tid & 3) * 8);
#pragma unroll
            for (int i = 0; i < 4; i++) {
                int t = tid + 256 * i;
                int c = t >> 3, ch = t & 7;
                cp16(bufb + 64 * KROW + c * VROW + ch * 16, vbase + (size_t)c * N_ + ch * 8);
            }
            CP_COMMIT();
        }

        __syncthreads();
        uint32_t qa[2][4];
        ldsm4(qa[0], qaddr);
        ldsm4(qa[1], qaddr + 32);

        float Dn[16][4];
#pragma unroll
        for (int c = 0; c < 16; c++)
#pragma unroll
            for (int p = 0; p < 4; p++) Dn[c][p] = 0.f;
        float den0 = 0.f, den1 = 0.f;

        for (int js = 0; js < NSTEP; js++) {
            uint32_t bufb = sb + SM_K0 + (js & 1) * BUFD;
            // issue async loads for next tile into the other buffer
            if (js + 1 < NSTEP) {
                int jt2 = (js + 1) * TJ;
                uint32_t nb = sb + SM_K0 + ((js + 1) & 1) * BUFD;
                cp16(nb + kdst, kbase + (size_t)(jt2 + (tid >> 2)) * C8_ + (tid & 3) * 8);
#pragma unroll
                for (int i = 0; i < 4; i++) {
                    int t = tid + 256 * i;
                    int c = t >> 3, ch = t & 7;
                    cp16(nb + 64 * KROW + c * VROW + ch * 16, vbase + (size_t)c * N_ + jt2 + ch * 8);
                }
            }
            CP_COMMIT();
            CP_WAIT1();          // current buffer's group complete
            __syncthreads();

            // ---- GEMM1: S[16 x 64] = Q . K^T ----
            float s[8][4];
#pragma unroll
            for (int t = 0; t < 8; t++)
#pragma unroll
                for (int p = 0; p < 4; p++) s[t][p] = 0.f;
#pragma unroll
            for (int kc = 0; kc < 2; kc++) {
#pragma unroll
                for (int tp = 0; tp < 4; tp++) {
                    uint32_t kb[4];
                    ldsm4(kb, bufb + koff + tp * 16 * KROW + kc * 32);
                    mma16816(s[2 * tp],     qa[kc], kb[0], kb[1]);
                    mma16816(s[2 * tp + 1], qa[kc], kb[2], kb[3]);
                }
            }
            // ---- exp + pack to bf16 A-fragments, accumulate denominator ----
            uint32_t pa[8], pb[8];
#pragma unroll
            for (int t = 0; t < 8; t++) {
                float e0 = __expf(s[t][0]), e1 = __expf(s[t][1]);
                float e2 = __expf(s[t][2]), e3 = __expf(s[t][3]);
                den0 += e0 + e1;
                den1 += e2 + e3;
                pa[t] = packbf2(e0, e1);
                pb[t] = packbf2(e2, e3);
            }
            // ---- GEMM2: D[16 x TC] += P . V^T ----
#pragma unroll
            for (int ctp = 0; ctp < TC / 16; ctp++) {
#pragma unroll
                for (int tp = 0; tp < 4; tp++) {
                    uint32_t vb[4];
                    ldsm4(vb, bufb + voff + ctp * 16 * VROW + tp * 32);
                    uint32_t af[4] = {pa[2 * tp], pb[2 * tp], pa[2 * tp + 1], pb[2 * tp + 1]};
                    mma16816(Dn[2 * ctp],     af, vb[0], vb[1]);
                    mma16816(Dn[2 * ctp + 1], af, vb[2], vb[3]);
                }
            }
            __syncthreads();   // all reads of this buffer done before it is refilled
        }

        // row denominators (rows are warp-private; reduce over the 4 lanes of a row)
        den0 += __shfl_xor_sync(0xffffffffu, den0, 1);
        den0 += __shfl_xor_sync(0xffffffffu, den0, 2);
        den1 += __shfl_xor_sync(0xffffffffu, den1, 1);
        den1 += __shfl_xor_sync(0xffffffffu, den1, 2);
        float inv0 = 1.f / den0, inv1 = 1.f / den1;

        // normalize + accumulate into g_acc[b][c][n]
        int n0 = itile + wrow + (lane >> 2);
        int cbase0 = cbase + 2 * (lane & 3);
        float* accb = g_acc + (size_t)b * C_ * N_;
#pragma unroll
        for (int ct = 0; ct < 16; ct++) {
            int c = 8 * ct + cbase0;
            float* p0 = accb + (size_t)c * N_ + n0;
            float* p1 = p0 + N_;
            float v0 = Dn[ct][0] * inv0, v1 = Dn[ct][1] * inv0;
            float v2 = Dn[ct][2] * inv1, v3 = Dn[ct][3] * inv1;
            if (kk == 0) {
                p0[0] = v0; p1[0] = v1; p0[8] = v2; p1[8] = v3;
            } else {
                p0[0] += v0; p1[0] += v1; p0[8] += v2; p1[8] += v3;
            }
        }
    }
}

// ---------------------------------------------------------------------------
// q projection -> g_q bf16 [zb][n][32]
__global__ void proj_q_kernel(const float* __restrict__ xball,
                              const float* __restrict__ W,
                              const float* __restrict__ bias) {
    __shared__ float Ws[C_ * C8_];
    int tid = threadIdx.x;
    for (int idx = tid; idx < C_ * C8_; idx += 128) {
        int o = idx >> 8, c = idx & 255;
        Ws[c * C8_ + o] = W[idx];
    }
    __syncthreads();
    int z = blockIdx.z * B_ + blockIdx.y;
    int n = blockIdx.x * 128 + tid;
    const float* xb = xball + (size_t)z * C_ * N_;
    float acc[C8_];
#pragma unroll
    for (int o = 0; o < C8_; o++) acc[o] = bias[o];
    for (int c = 0; c < C_; c++) {
        float xv = xb[c * N_ + n];
#pragma unroll
        for (int o = 0; o < C8_; o++) acc[o] = fmaf(Ws[c * C8_ + o], xv, acc[o]);
    }
    __nv_bfloat162* op = (__nv_bfloat162*)(g_q + ((size_t)z * N_ + n) * C8_);
#pragma unroll
    for (int o = 0; o < C8_; o += 2)
        op[o >> 1] = __float22bfloat162_rn(make_float2(acc[o], acc[o + 1]));
}

// k projection -> g_k bf16 [b][n][32]
__global__ void proj_k_kernel(const float* __restrict__ x,
                              const float* __restrict__ W,
                              const float* __restrict__ bias) {
    __shared__ float Ws[C_ * C8_];
    int tid = threadIdx.x;
    for (int idx = tid; idx < C_ * C8_; idx += 128) {
        int o = idx >> 8, c = idx & 255;
        Ws[c * C8_ + o] = W[idx];
    }
    __syncthreads();
    int b = blockIdx.y;
    int n = blockIdx.x * 128 + tid;
    const float* xb = x + (size_t)b * C_ * N_;
    float acc[C8_];
#pragma unroll
    for (int o = 0; o < C8_; o++) acc[o] = bias[o];
    for (int c = 0; c < C_; c++) {
        float xv = xb[c * N_ + n];
#pragma unroll
        for (int o = 0; o < C8_; o++) acc[o] = fmaf(Ws[c * C8_ + o], xv, acc[o]);
    }
    __nv_bfloat162* op = (__nv_bfloat162*)(g_k + ((size_t)b * N_ + n) * C8_);
#pragma unroll
    for (int o = 0; o < C8_; o += 2)
        op[o >> 1] = __float22bfloat162_rn(make_float2(acc[o], acc[o + 1]));
}

// v projection -> g_v bf16 [zb][c][n]; each thread handles 2 n-values
__global__ void proj_v_kernel(const float* __restrict__ xball,
                              const float* __restrict__ W,
                              const float* __restrict__ bias) {
    __shared__ float Ws[C_ * 32];
    int tid = threadIdx.x;
    int z = blockIdx.z;
    int cbase = blockIdx.y * 32;
    for (int idx = tid; idx < 32 * C_; idx += 128) {
        int orel = idx >> 8, c = idx & 255;
        Ws[c * 32 + orel] = W[(size_t)(cbase + orel) * C_ + c];
    }
    __syncthreads();
    int n = blockIdx.x * 256 + tid;   // n and n+128
    const float* xb = xball + (size_t)z * C_ * N_;
    float acc0[32], acc1[32];
#pragma unroll
    for (int o = 0; o < 32; o++) { acc0[o] = bias[cbase + o]; acc1[o] = acc0[o]; }
    for (int c = 0; c < C_; c++) {
        float xv0 = xb[c * N_ + n];
        float xv1 = xb[c * N_ + n + 128];
#pragma unroll
        for (int o = 0; o < 32; o++) {
            float w = Ws[c * 32 + o];
            acc0[o] = fmaf(w, xv0, acc0[o]);
            acc1[o] = fmaf(w, xv1, acc1[o]);
        }
    }
    __nv_bfloat16* out = g_v + ((size_t)z * C_ + cbase) * N_;
#pragma unroll
    for (int o = 0; o < 32; o++) {
        out[(size_t)o * N_ + n]       = __float2bfloat16(acc0[o]);
        out[(size_t)o * N_ + n + 128] = __float2bfloat16(acc1[o]);
    }
}

// final: out[b][o][n] = bf[o] + sum_c Wf[o][c]*gamma*acc + Wf[o][C+c]*xf
// each thread handles 2 n-values
__global__ void final_kernel(const float* __restrict__ xf,
                             const float* __restrict__ Wf,
                             const float* __restrict__ bf,
                             const float* __restrict__ gptr,
                             float* __restrict__ out) {
    __shared__ float Ws[16 * 512];
    int tid = threadIdx.x;
    int b = blockIdx.z;
    int obase = blockIdx.y * 16;
    for (int idx = tid; idx < 16 * 512; idx += 128)
        Ws[idx] = Wf[(size_t)obase * 512 + idx];
    __syncthreads();
    int n = blockIdx.x * 256 + tid;   // n and n+128
    float gamma = gptr[0];
    const float* xb = xf + (size_t)b * C_ * N_;
    const float* ab = g_acc + (size_t)b * C_ * N_;
    float acc0[16], acc1[16];
#pragma unroll
    for (int o = 0; o < 16; o++) { acc0[o] = bf[obase + o]; acc1[o] = acc0[o]; }
    for (int c = 0; c < C_; c++) {
        float av0 = ab[c * N_ + n] * gamma;
        float av1 = ab[c * N_ + n + 128] * gamma;
        float xv0 = xb[c * N_ + n];
        float xv1 = xb[c * N_ + n + 128];
#pragma unroll
        for (int o = 0; o < 16; o++) {
            float wa = Ws[o * 512 + c];
            float wx = Ws[o * 512 + 256 + c];
            acc0[o] = fmaf(wa, av0, acc0[o]);
            acc0[o] = fmaf(wx, xv0, acc0[o]);
            acc1[o] = fmaf(wa, av1, acc1[o]);
            acc1[o] = fmaf(wx, xv1, acc1[o]);
        }
    }
#pragma unroll
    for (int o = 0; o < 16; o++) {
        float* p = out + ((size_t)b * C_ + obase + o) * N_ + n;
        p[0] = acc0[o];
        p[128] = acc1[o];
    }
}

// ---------------------------------------------------------------------------
extern "C" void kernel_launch(void* const* d_in, const int* in_sizes, int n_in,
                              void* d_out, int out_size) {
    const float* x_f = (const float*)d_in[0];
    const float* x_b = (const float*)d_in[1];
    const float* Wq  = (const float*)d_in[2];
    const float* bq  = (const float*)d_in[3];
    const float* Wk  = (const float*)d_in[4];
    const float* bk  = (const float*)d_in[5];
    const float* Wv  = (const float*)d_in[6];
    const float* bv  = (const float*)d_in[7];
    const float* Wf  = (const float*)d_in[8];
    const float* bf  = (const float*)d_in[9];
    const float* gm  = (const float*)d_in[10];
    float* out = (float*)d_out;

    cudaFuncSetAttribute(attn_kernel, cudaFuncAttributeMaxDynamicSharedMemorySize, SM_TOTAL);

    proj_k_kernel<<<dim3(N_ / 128, B_), 128>>>(x_f, Wk, bk);
    proj_q_kernel<<<dim3(N_ / 128, B_, K_), 128>>>(x_b, Wq, bq);
    proj_v_kernel<<<dim3(N_ / 256, C_ / 32, K_ * B_), 128>>>(x_b, Wv, bv);
    attn_kernel<<<dim3(N_ / TI, C_ / TC, B_), 256, SM_TOTAL>>>();
    final_kernel<<<dim3(N_ / 256, C_ / 16, B_), 128>>>(x_f, Wf, bf, gm, out);
}

// round 8
// speedup vs baseline: 6.1259x; 1.3333x over previous
#include <cuda_runtime.h>
#include <cuda_bf16.h>
#include <cstdint>
#include <math.h>

constexpr int B_  = 4;
constexpr int C_  = 256;
constexpr int C8_ = 32;
constexpr int N_  = 4096;
constexpr int K_  = 3;

constexpr int TI = 128;   // queries per CTA
constexpr int TJ = 64;    // keys per j-step
constexpr int TC = 128;   // channels per CTA (split across blockIdx.y)
constexpr int NSTEP = N_ / TJ;

// ---- scratch (device globals; no allocation allowed) ----------------------
__device__ __nv_bfloat16 g_q[(size_t)K_ * B_ * N_ * C8_];   // [kk*B+b][n][o]
__device__ __nv_bfloat16 g_k[(size_t)B_ * N_ * C8_];        // [b][n][o]
__device__ __nv_bfloat16 g_v[(size_t)K_ * B_ * C_ * N_];    // [kk*B+b][c][n]
__device__ float         g_acc[(size_t)B_ * C_ * N_];       // [b][c][n]

// ---- helpers --------------------------------------------------------------
__device__ __forceinline__ uint32_t smem_u32(const void* p) {
    uint32_t a;
    asm("{ .reg .u64 t; cvta.to.shared.u64 t, %1; cvt.u32.u64 %0, t; }" : "=r"(a) : "l"(p));
    return a;
}
__device__ __forceinline__ void ldsm4(uint32_t* r, uint32_t addr) {
    asm volatile("ldmatrix.sync.aligned.m8n8.x4.shared.b16 {%0,%1,%2,%3}, [%4];"
                 : "=r"(r[0]), "=r"(r[1]), "=r"(r[2]), "=r"(r[3]) : "r"(addr));
}
__device__ __forceinline__ void mma16816(float* d, const uint32_t* a, uint32_t b0, uint32_t b1) {
    asm volatile("mma.sync.aligned.m16n8k16.row.col.f32.bf16.bf16.f32 "
                 "{%0,%1,%2,%3}, {%4,%5,%6,%7}, {%8,%9}, {%0,%1,%2,%3};"
                 : "+f"(d[0]), "+f"(d[1]), "+f"(d[2]), "+f"(d[3])
                 : "r"(a[0]), "r"(a[1]), "r"(a[2]), "r"(a[3]), "r"(b0), "r"(b1));
}
__device__ __forceinline__ uint32_t packbf2(float x, float y) {
    __nv_bfloat162 h = __float22bfloat162_rn(make_float2(x, y));
    return *(uint32_t*)&h;
}
__device__ __forceinline__ void cp16(uint32_t dst, const void* src) {
    asm volatile("cp.async.cg.shared.global [%0], [%1], 16;" :: "r"(dst), "l"(src));
}
#define CP_COMMIT() asm volatile("cp.async.commit_group;" ::: "memory")
#define CP_WAIT1()  asm volatile("cp.async.wait_group 1;" ::: "memory")

// ---- smem layout: padded row strides, conflict-free for ldmatrix ----------
constexpr int QROW = 80;    // 64B data + 16B pad
constexpr int KROW = 80;
constexpr int VROW = 144;   // 128B data + 16B pad
constexpr int SM_Q  = 0;                      // 128 * 80  = 10240
constexpr int SM_K0 = 10240;
constexpr int BUFD  = 64 * KROW + TC * VROW;  // 23552
constexpr int SM_TOTAL = SM_K0 + 2 * BUFD;    // 57344

// ---------------------------------------------------------------------------
// attention: 128 threads, 4 warps, M=32 rows/warp (2 A-tiles reuse each B frag)
__global__ void __launch_bounds__(128, 2) attn_kernel() {
    extern __shared__ char smem[];
    uint32_t sb = smem_u32(smem);
    int tid = threadIdx.x, wid = tid >> 5, lane = tid & 31;
    int b = blockIdx.z;
    int cbase = blockIdx.y * TC;
    int itile = blockIdx.x * TI;
    int wrow = wid * 32;

    uint32_t qaddr = sb + SM_Q + (wrow + (lane & 15)) * QROW + ((lane >> 4) & 1) * 16;
    uint32_t koff = ((lane >> 4) * 8 + (lane & 7)) * KROW + ((lane >> 3) & 1) * 16;
    uint32_t voff = 64 * KROW + ((lane >> 4) * 8 + (lane & 7)) * VROW + ((lane >> 3) & 1) * 16;

    const __nv_bfloat16* kbase = g_k + (size_t)b * N_ * C8_;

    for (int kk = 0; kk < K_; kk++) {
        size_t zb = (size_t)kk * B_ + b;
        const __nv_bfloat16* vbase = g_v + (zb * C_ + cbase) * (size_t)N_;
        __syncthreads();
        // Q tile -> smem (128 rows x 64B)
        const __nv_bfloat16* qp = g_q + (zb * N_ + itile) * C8_;
        for (int t = tid; t < 512; t += 128) {
            int r = t >> 2, ch = t & 3;
            *(uint4*)(smem + SM_Q + r * QROW + ch * 16) = *(const uint4*)(qp + r * C8_ + ch * 8);
        }

        // prologue: async-load K,V tile 0 into buffer 0
        {
            uint32_t bufb = sb + SM_K0;
#pragma unroll
            for (int i = 0; i < 2; i++) {
                int t = tid + 128 * i;
                int r = t >> 2, ch = t & 3;
                cp16(bufb + r * KROW + ch * 16, kbase + (size_t)r * C8_ + ch * 8);
            }
#pragma unroll
            for (int i = 0; i < 8; i++) {
                int t = tid + 128 * i;
                int c = t >> 3, ch = t & 7;
                cp16(bufb + 64 * KROW + c * VROW + ch * 16, vbase + (size_t)c * N_ + ch * 8);
            }
            CP_COMMIT();
        }

        __syncthreads();
        uint32_t qa[2][2][4];   // [Mtile][kc]
#pragma unroll
        for (int t = 0; t < 2; t++) {
            ldsm4(qa[t][0], qaddr + t * 16 * QROW);
            ldsm4(qa[t][1], qaddr + t * 16 * QROW + 32);
        }

        float Dn[2][16][4];
#pragma unroll
        for (int t = 0; t < 2; t++)
#pragma unroll
            for (int c = 0; c < 16; c++)
#pragma unroll
                for (int p = 0; p < 4; p++) Dn[t][c][p] = 0.f;
        float den[2][2] = {{0.f, 0.f}, {0.f, 0.f}};

        for (int js = 0; js < NSTEP; js++) {
            uint32_t bufb = sb + SM_K0 + (js & 1) * BUFD;
            if (js + 1 < NSTEP) {
                int jt2 = (js + 1) * TJ;
                uint32_t nb = sb + SM_K0 + ((js + 1) & 1) * BUFD;
#pragma unroll
                for (int i = 0; i < 2; i++) {
                    int t = tid + 128 * i;
                    int r = t >> 2, ch = t & 3;
                    cp16(nb + r * KROW + ch * 16, kbase + (size_t)(jt2 + r) * C8_ + ch * 8);
                }
#pragma unroll
                for (int i = 0; i < 8; i++) {
                    int t = tid + 128 * i;
                    int c = t >> 3, ch = t & 7;
                    cp16(nb + 64 * KROW + c * VROW + ch * 16, vbase + (size_t)c * N_ + jt2 + ch * 8);
                }
            }
            CP_COMMIT();
            CP_WAIT1();
            __syncthreads();

            // ---- GEMM1: S[32 x 64] = Q . K^T ----
            float s[2][8][4];
#pragma unroll
            for (int t = 0; t < 2; t++)
#pragma unroll
                for (int j = 0; j < 8; j++)
#pragma unroll
                    for (int p = 0; p < 4; p++) s[t][j][p] = 0.f;
#pragma unroll
            for (int kc = 0; kc < 2; kc++) {
#pragma unroll
                for (int jp = 0; jp < 4; jp++) {
                    uint32_t kb[4];
                    ldsm4(kb, bufb + koff + jp * 16 * KROW + kc * 32);
#pragma unroll
                    for (int t = 0; t < 2; t++) {
                        mma16816(s[t][2 * jp],     qa[t][kc], kb[0], kb[1]);
                        mma16816(s[t][2 * jp + 1], qa[t][kc], kb[2], kb[3]);
                    }
                }
            }
            // ---- exp + pack, accumulate denominators ----
            uint32_t pa[2][8], pb[2][8];
#pragma unroll
            for (int t = 0; t < 2; t++) {
#pragma unroll
                for (int j = 0; j < 8; j++) {
                    float e0 = __expf(s[t][j][0]), e1 = __expf(s[t][j][1]);
                    float e2 = __expf(s[t][j][2]), e3 = __expf(s[t][j][3]);
                    den[t][0] += e0 + e1;
                    den[t][1] += e2 + e3;
                    pa[t][j] = packbf2(e0, e1);
                    pb[t][j] = packbf2(e2, e3);
                }
            }
            // ---- GEMM2: D[32 x TC] += P . V^T ----
#pragma unroll
            for (int vp = 0; vp < 8; vp++) {
#pragma unroll
                for (int tp = 0; tp < 4; tp++) {
                    uint32_t vb[4];
                    ldsm4(vb, bufb + voff + vp * 16 * VROW + tp * 32);
#pragma unroll
                    for (int t = 0; t < 2; t++) {
                        uint32_t af[4] = {pa[t][2 * tp], pb[t][2 * tp],
                                          pa[t][2 * tp + 1], pb[t][2 * tp + 1]};
                        mma16816(Dn[t][2 * vp],     af, vb[0], vb[1]);
                        mma16816(Dn[t][2 * vp + 1], af, vb[2], vb[3]);
                    }
                }
            }
            __syncthreads();
        }

        // denominators: reduce over the 4 lanes of each row
        float inv[2][2];
#pragma unroll
        for (int t = 0; t < 2; t++)
#pragma unroll
            for (int h = 0; h < 2; h++) {
                float d = den[t][h];
                d += __shfl_xor_sync(0xffffffffu, d, 1);
                d += __shfl_xor_sync(0xffffffffu, d, 2);
                inv[t][h] = 1.f / d;
            }

        // normalize + accumulate into g_acc[b][c][n]
        float* accb = g_acc + (size_t)b * C_ * N_;
        int cb0 = cbase + 2 * (lane & 3);
#pragma unroll
        for (int t = 0; t < 2; t++) {
            int n0 = itile + wrow + t * 16 + (lane >> 2);
#pragma unroll
            for (int ct = 0; ct < 16; ct++) {
                int c = cb0 + 8 * ct;
                float* p0 = accb + (size_t)c * N_ + n0;
                float* p1 = p0 + N_;
                float v0 = Dn[t][ct][0] * inv[t][0], v1 = Dn[t][ct][1] * inv[t][0];
                float v2 = Dn[t][ct][2] * inv[t][1], v3 = Dn[t][ct][3] * inv[t][1];
                if (kk == 0) {
                    p0[0] = v0; p1[0] = v1; p0[8] = v2; p1[8] = v3;
                } else {
                    p0[0] += v0; p1[0] += v1; p0[8] += v2; p1[8] += v3;
                }
            }
        }
    }
}

// ---------------------------------------------------------------------------
// v projection via bf16 tensor cores: g_v[z][c][n] = Wv[c][:].x[:][n] + bv[c]
constexpr int WROW = 144;   // 64 bf16 = 128B + 16 pad
constexpr int XROW = 144;

__global__ void __launch_bounds__(128, 2) proj_v_kernel(const float* __restrict__ xball,
                                                        const float* __restrict__ W,
                                                        const float* __restrict__ bias) {
    __shared__ char sm[128 * WROW + 128 * XROW];
    uint32_t wt_b = smem_u32(sm);
    uint32_t xt_b = wt_b + 128 * WROW;
    int tid = threadIdx.x, wid = tid >> 5, lane = tid & 31;
    int z = blockIdx.z;
    int cbase = blockIdx.y * 128;
    int n0 = blockIdx.x * 128;
    int wrow = wid * 32;
    const float* xb = xball + (size_t)z * C_ * N_;

    uint32_t waddr = wt_b + (wrow + (lane & 15)) * WROW + ((lane >> 4) & 1) * 16;
    uint32_t xaddr = xt_b + ((lane >> 4) * 8 + (lane & 7)) * XROW + ((lane >> 3) & 1) * 16;

    float acc[2][16][4];
#pragma unroll
    for (int t = 0; t < 2; t++) {
        float b0 = bias[cbase + wrow + t * 16 + (lane >> 2)];
        float b1 = bias[cbase + wrow + t * 16 + (lane >> 2) + 8];
#pragma unroll
        for (int nt = 0; nt < 16; nt++) {
            acc[t][nt][0] = b0; acc[t][nt][1] = b0;
            acc[t][nt][2] = b1; acc[t][nt][3] = b1;
        }
    }

    for (int ks = 0; ks < 4; ks++) {
        int k0 = ks * 64;
        __syncthreads();
        // W tile [128c][64k] fp32 -> bf16
#pragma unroll
        for (int i = 0; i < 16; i++) {
            int idx = tid + 128 * i;
            int r = idx >> 4, kq = idx & 15;
            float4 w4 = *(const float4*)(W + (size_t)(cbase + r) * C_ + k0 + kq * 4);
            uint32_t lo = packbf2(w4.x, w4.y), hi = packbf2(w4.z, w4.w);
            uint32_t d = wt_b + r * WROW + kq * 8;
            asm volatile("st.shared.v2.b32 [%0], {%1, %2};" :: "r"(d), "r"(lo), "r"(hi));
        }
        // x^T tile [128n][64k] fp32 -> bf16 (transpose during load)
        {
            int n = tid;
#pragma unroll
            for (int kg = 0; kg < 16; kg++) {
                int k = k0 + kg * 4;
                float a0 = xb[(size_t)(k + 0) * N_ + n0 + n];
                float a1 = xb[(size_t)(k + 1) * N_ + n0 + n];
                float a2 = xb[(size_t)(k + 2) * N_ + n0 + n];
                float a3 = xb[(size_t)(k + 3) * N_ + n0 + n];
                uint32_t lo = packbf2(a0, a1), hi = packbf2(a2, a3);
                uint32_t d = xt_b + n * XROW + kg * 8;
                asm volatile("st.shared.v2.b32 [%0], {%1, %2};" :: "r"(d), "r"(lo), "r"(hi));
            }
        }
        __syncthreads();

#pragma unroll
        for (int q = 0; q < 4; q++) {
            uint32_t af[2][4];
#pragma unroll
            for (int t = 0; t < 2; t++)
                ldsm4(af[t], waddr + t * 16 * WROW + q * 32);
#pragma unroll
            for (int np = 0; np < 8; np++) {
                uint32_t xb4[4];
                ldsm4(xb4, xaddr + np * 16 * XROW + q * 32);
#pragma unroll
                for (int t = 0; t < 2; t++) {
                    mma16816(acc[t][2 * np],     af[t], xb4[0], xb4[1]);
                    mma16816(acc[t][2 * np + 1], af[t], xb4[2], xb4[3]);
                }
            }
        }
    }

    // writeback bf16
    __nv_bfloat16* outb = g_v + (size_t)z * C_ * N_;
#pragma unroll
    for (int t = 0; t < 2; t++) {
        int c0 = cbase + wrow + t * 16 + (lane >> 2);
#pragma unroll
        for (int nt = 0; nt < 16; nt++) {
            int n = n0 + nt * 8 + 2 * (lane & 3);
            uint32_t lo = packbf2(acc[t][nt][0], acc[t][nt][1]);
            uint32_t hi = packbf2(acc[t][nt][2], acc[t][nt][3]);
            *(uint32_t*)(outb + (size_t)c0 * N_ + n) = lo;
            *(uint32_t*)(outb + (size_t)(c0 + 8) * N_ + n) = hi;
        }
    }
}

// ---------------------------------------------------------------------------
// q projection -> g_q bf16 [zb][n][32]
__global__ void proj_q_kernel(const float* __restrict__ xball,
                              const float* __restrict__ W,
                              const float* __restrict__ bias) {
    __shared__ float Ws[C_ * C8_];
    int tid = threadIdx.x;
    for (int idx = tid; idx < C_ * C8_; idx += 128) {
        int o = idx >> 8, c = idx & 255;
        Ws[c * C8_ + o] = W[idx];
    }
    __syncthreads();
    int z = blockIdx.z * B_ + blockIdx.y;
    int n = blockIdx.x * 128 + tid;
    const float* xb = xball + (size_t)z * C_ * N_;
    float acc[C8_];
#pragma unroll
    for (int o = 0; o < C8_; o++) acc[o] = bias[o];
    for (int c = 0; c < C_; c++) {
        float xv = xb[c * N_ + n];
#pragma unroll
        for (int o = 0; o < C8_; o++) acc[o] = fmaf(Ws[c * C8_ + o], xv, acc[o]);
    }
    __nv_bfloat162* op = (__nv_bfloat162*)(g_q + ((size_t)z * N_ + n) * C8_);
#pragma unroll
    for (int o = 0; o < C8_; o += 2)
        op[o >> 1] = __float22bfloat162_rn(make_float2(acc[o], acc[o + 1]));
}

// k projection -> g_k bf16 [b][n][32]
__global__ void proj_k_kernel(const float* __restrict__ x,
                              const float* __restrict__ W,
                              const float* __restrict__ bias) {
    __shared__ float Ws[C_ * C8_];
    int tid = threadIdx.x;
    for (int idx = tid; idx < C_ * C8_; idx += 128) {
        int o = idx >> 8, c = idx & 255;
        Ws[c * C8_ + o] = W[idx];
    }
    __syncthreads();
    int b = blockIdx.y;
    int n = blockIdx.x * 128 + tid;
    const float* xb = x + (size_t)b * C_ * N_;
    float acc[C8_];
#pragma unroll
    for (int o = 0; o < C8_; o++) acc[o] = bias[o];
    for (int c = 0; c < C_; c++) {
        float xv = xb[c * N_ + n];
#pragma unroll
        for (int o = 0; o < C8_; o++) acc[o] = fmaf(Ws[c * C8_ + o], xv, acc[o]);
    }
    __nv_bfloat162* op = (__nv_bfloat162*)(g_k + ((size_t)b * N_ + n) * C8_);
#pragma unroll
    for (int o = 0; o < C8_; o += 2)
        op[o >> 1] = __float22bfloat162_rn(make_float2(acc[o], acc[o + 1]));
}

// final: out[b][o][n] = bf[o] + sum_c Wf[o][c]*gamma*acc + Wf[o][C+c]*xf
__global__ void final_kernel(const float* __restrict__ xf,
                             const float* __restrict__ Wf,
                             const float* __restrict__ bf,
                             const float* __restrict__ gptr,
                             float* __restrict__ out) {
    __shared__ float Ws[16 * 512];
    int tid = threadIdx.x;
    int b = blockIdx.z;
    int obase = blockIdx.y * 16;
    for (int idx = tid; idx < 16 * 512; idx += 128)
        Ws[idx] = Wf[(size_t)obase * 512 + idx];
    __syncthreads();
    int n = blockIdx.x * 256 + tid;   // n and n+128
    float gamma = gptr[0];
    const float* xb = xf + (size_t)b * C_ * N_;
    const float* ab = g_acc + (size_t)b * C_ * N_;
    float acc0[16], acc1[16];
#pragma unroll
    for (int o = 0; o < 16; o++) { acc0[o] = bf[obase + o]; acc1[o] = acc0[o]; }
    for (int c = 0; c < C_; c++) {
        float av0 = ab[c * N_ + n] * gamma;
        float av1 = ab[c * N_ + n + 128] * gamma;
        float xv0 = xb[c * N_ + n];
        float xv1 = xb[c * N_ + n + 128];
#pragma unroll
        for (int o = 0; o < 16; o++) {
            float wa = Ws[o * 512 + c];
            float wx = Ws[o * 512 + 256 + c];
            acc0[o] = fmaf(wa, av0, acc0[o]);
            acc0[o] = fmaf(wx, xv0, acc0[o]);
            acc1[o] = fmaf(wa, av1, acc1[o]);
            acc1[o] = fmaf(wx, xv1, acc1[o]);
        }
    }
#pragma unroll
    for (int o = 0; o < 16; o++) {
        float* p = out + ((size_t)b * C_ + obase + o) * N_ + n;
        p[0] = acc0[o];
        p[128] = acc1[o];
    }
}

// ---------------------------------------------------------------------------
extern "C" void kernel_launch(void* const* d_in, const int* in_sizes, int n_in,
                              void* d_out, int out_size) {
    const float* x_f = (const float*)d_in[0];
    const float* x_b = (const float*)d_in[1];
    const float* Wq  = (const float*)d_in[2];
    const float* bq  = (const float*)d_in[3];
    const float* Wk  = (const float*)d_in[4];
    const float* bk  = (const float*)d_in[5];
    const float* Wv  = (const float*)d_in[6];
    const float* bv  = (const float*)d_in[7];
    const float* Wf  = (const float*)d_in[8];
    const float* bf  = (const float*)d_in[9];
    const float* gm  = (const float*)d_in[10];
    float* out = (float*)d_out;

    cudaFuncSetAttribute(attn_kernel, cudaFuncAttributeMaxDynamicSharedMemorySize, SM_TOTAL);

    proj_k_kernel<<<dim3(N_ / 128, B_), 128>>>(x_f, Wk, bk);
    proj_q_kernel<<<dim3(N_ / 128, B_, K_), 128>>>(x_b, Wq, bq);
    proj_v_kernel<<<dim3(N_ / 128, C_ / 128, K_ * B_), 128>>>(x_b, Wv, bv);
    attn_kernel<<<dim3(N_ / TI, C_ / TC, B_), 128, SM_TOTAL>>>();
    final_kernel<<<dim3(N_ / 256, C_ / 16, B_), 128>>>(x_f, Wf, bf, gm, out);
}

// round 9
// speedup vs baseline: 9.3280x; 1.5227x over previous
#include <cuda_runtime.h>
#include <cuda_bf16.h>
#include <cstdint>
#include <math.h>

constexpr int B_  = 4;
constexpr int C_  = 256;
constexpr int C8_ = 32;
constexpr int N_  = 4096;
constexpr int K_  = 3;

constexpr int TI = 128;   // queries per CTA
constexpr int TJ = 64;    // keys per j-step
constexpr int TC = 128;   // channels per CTA (split across blockIdx.y)
constexpr int NSTEP = N_ / TJ;

// ---- scratch (device globals; no allocation allowed) ----------------------
__device__ __nv_bfloat16 g_q[(size_t)K_ * B_ * N_ * C8_];   // [kk*B+b][n][o]
__device__ __nv_bfloat16 g_k[(size_t)B_ * N_ * C8_];        // [b][n][o]
__device__ __nv_bfloat16 g_v[(size_t)K_ * B_ * C_ * N_];    // [kk*B+b][c][n]
__device__ float         g_acc[(size_t)B_ * C_ * N_];       // [b][c][n]

// ---- helpers --------------------------------------------------------------
__device__ __forceinline__ uint32_t smem_u32(const void* p) {
    uint32_t a;
    asm("{ .reg .u64 t; cvta.to.shared.u64 t, %1; cvt.u32.u64 %0, t; }" : "=r"(a) : "l"(p));
    return a;
}
__device__ __forceinline__ void ldsm4(uint32_t* r, uint32_t addr) {
    asm volatile("ldmatrix.sync.aligned.m8n8.x4.shared.b16 {%0,%1,%2,%3}, [%4];"
                 : "=r"(r[0]), "=r"(r[1]), "=r"(r[2]), "=r"(r[3]) : "r"(addr));
}
__device__ __forceinline__ void mma16816(float* d, const uint32_t* a, uint32_t b0, uint32_t b1) {
    asm volatile("mma.sync.aligned.m16n8k16.row.col.f32.bf16.bf16.f32 "
                 "{%0,%1,%2,%3}, {%4,%5,%6,%7}, {%8,%9}, {%0,%1,%2,%3};"
                 : "+f"(d[0]), "+f"(d[1]), "+f"(d[2]), "+f"(d[3])
                 : "r"(a[0]), "r"(a[1]), "r"(a[2]), "r"(a[3]), "r"(b0), "r"(b1));
}
__device__ __forceinline__ uint32_t packbf2(float x, float y) {
    __nv_bfloat162 h = __float22bfloat162_rn(make_float2(x, y));
    return *(uint32_t*)&h;
}
__device__ __forceinline__ void cp16(uint32_t dst, const void* src) {
    asm volatile("cp.async.cg.shared.global [%0], [%1], 16;" :: "r"(dst), "l"(src));
}
#define CP_COMMIT() asm volatile("cp.async.commit_group;" ::: "memory")
#define CP_WAIT1()  asm volatile("cp.async.wait_group 1;" ::: "memory")

// ---- smem layout: padded row strides, conflict-free for ldmatrix ----------
constexpr int QROW = 80;    // 64B data + 16B pad
constexpr int KROW = 80;
constexpr int VROW = 144;   // 128B data + 16B pad
constexpr int SM_Q  = 0;                      // 128 * 80  = 10240
constexpr int SM_K0 = 10240;
constexpr int BUFD  = 64 * KROW + TC * VROW;  // 23552
constexpr int SM_TOTAL = SM_K0 + 2 * BUFD;    // 57344

// ---------------------------------------------------------------------------
// attention: 128 threads, 4 warps, M=32 rows/warp
__global__ void __launch_bounds__(128, 2) attn_kernel() {
    extern __shared__ char smem[];
    uint32_t sb = smem_u32(smem);
    int tid = threadIdx.x, wid = tid >> 5, lane = tid & 31;
    int b = blockIdx.z;
    int cbase = blockIdx.y * TC;
    int itile = blockIdx.x * TI;
    int wrow = wid * 32;

    uint32_t qaddr = sb + SM_Q + (wrow + (lane & 15)) * QROW + ((lane >> 4) & 1) * 16;
    uint32_t koff = ((lane >> 4) * 8 + (lane & 7)) * KROW + ((lane >> 3) & 1) * 16;
    uint32_t voff = 64 * KROW + ((lane >> 4) * 8 + (lane & 7)) * VROW + ((lane >> 3) & 1) * 16;

    const __nv_bfloat16* kbase = g_k + (size_t)b * N_ * C8_;

    for (int kk = 0; kk < K_; kk++) {
        size_t zb = (size_t)kk * B_ + b;
        const __nv_bfloat16* vbase = g_v + (zb * C_ + cbase) * (size_t)N_;
        __syncthreads();
        // Q tile -> smem (128 rows x 64B)
        const __nv_bfloat16* qp = g_q + (zb * N_ + itile) * C8_;
        for (int t = tid; t < 512; t += 128) {
            int r = t >> 2, ch = t & 3;
            *(uint4*)(smem + SM_Q + r * QROW + ch * 16) = *(const uint4*)(qp + r * C8_ + ch * 8);
        }

        // prologue: async-load K,V tile 0 into buffer 0
        {
            uint32_t bufb = sb + SM_K0;
#pragma unroll
            for (int i = 0; i < 2; i++) {
                int t = tid + 128 * i;
                int r = t >> 2, ch = t & 3;
                cp16(bufb + r * KROW + ch * 16, kbase + (size_t)r * C8_ + ch * 8);
            }
#pragma unroll
            for (int i = 0; i < 8; i++) {
                int t = tid + 128 * i;
                int c = t >> 3, ch = t & 7;
                cp16(bufb + 64 * KROW + c * VROW + ch * 16, vbase + (size_t)c * N_ + ch * 8);
            }
            CP_COMMIT();
        }

        __syncthreads();
        uint32_t qa[2][2][4];   // [Mtile][kc]
#pragma unroll
        for (int t = 0; t < 2; t++) {
            ldsm4(qa[t][0], qaddr + t * 16 * QROW);
            ldsm4(qa[t][1], qaddr + t * 16 * QROW + 32);
        }

        float Dn[2][16][4];
#pragma unroll
        for (int t = 0; t < 2; t++)
#pragma unroll
            for (int c = 0; c < 16; c++)
#pragma unroll
                for (int p = 0; p < 4; p++) Dn[t][c][p] = 0.f;
        float den[2][2] = {{0.f, 0.f}, {0.f, 0.f}};

        for (int js = 0; js < NSTEP; js++) {
            uint32_t bufb = sb + SM_K0 + (js & 1) * BUFD;
            if (js + 1 < NSTEP) {
                int jt2 = (js + 1) * TJ;
                uint32_t nb = sb + SM_K0 + ((js + 1) & 1) * BUFD;
#pragma unroll
                for (int i = 0; i < 2; i++) {
                    int t = tid + 128 * i;
                    int r = t >> 2, ch = t & 3;
                    cp16(nb + r * KROW + ch * 16, kbase + (size_t)(jt2 + r) * C8_ + ch * 8);
                }
#pragma unroll
                for (int i = 0; i < 8; i++) {
                    int t = tid + 128 * i;
                    int c = t >> 3, ch = t & 7;
                    cp16(nb + 64 * KROW + c * VROW + ch * 16, vbase + (size_t)c * N_ + jt2 + ch * 8);
                }
            }
            CP_COMMIT();
            CP_WAIT1();
            __syncthreads();

            // ---- GEMM1: S[32 x 64] = Q . K^T ----
            float s[2][8][4];
#pragma unroll
            for (int t = 0; t < 2; t++)
#pragma unroll
                for (int j = 0; j < 8; j++)
#pragma unroll
                    for (int p = 0; p < 4; p++) s[t][j][p] = 0.f;
#pragma unroll
            for (int kc = 0; kc < 2; kc++) {
#pragma unroll
                for (int jp = 0; jp < 4; jp++) {
                    uint32_t kb[4];
                    ldsm4(kb, bufb + koff + jp * 16 * KROW + kc * 32);
#pragma unroll
                    for (int t = 0; t < 2; t++) {
                        mma16816(s[t][2 * jp],     qa[t][kc], kb[0], kb[1]);
                        mma16816(s[t][2 * jp + 1], qa[t][kc], kb[2], kb[3]);
                    }
                }
            }
            // ---- exp + pack, accumulate denominators ----
            uint32_t pa[2][8], pb[2][8];
#pragma unroll
            for (int t = 0; t < 2; t++) {
#pragma unroll
                for (int j = 0; j < 8; j++) {
                    float e0 = __expf(s[t][j][0]), e1 = __expf(s[t][j][1]);
                    float e2 = __expf(s[t][j][2]), e3 = __expf(s[t][j][3]);
                    den[t][0] += e0 + e1;
                    den[t][1] += e2 + e3;
                    pa[t][j] = packbf2(e0, e1);
                    pb[t][j] = packbf2(e2, e3);
                }
            }
            // ---- GEMM2: D[32 x TC] += P . V^T ----
            // tp (K-chunk) OUTER so accumulator reuse distance is 32 mma, not 4
#pragma unroll
            for (int tp = 0; tp < 4; tp++) {
                uint32_t af[2][4];
#pragma unroll
                for (int t = 0; t < 2; t++) {
                    af[t][0] = pa[t][2 * tp];     af[t][1] = pb[t][2 * tp];
                    af[t][2] = pa[t][2 * tp + 1]; af[t][3] = pb[t][2 * tp + 1];
                }
#pragma unroll
                for (int vp = 0; vp < 8; vp++) {
                    uint32_t vb[4];
                    ldsm4(vb, bufb + voff + vp * 16 * VROW + tp * 32);
#pragma unroll
                    for (int t = 0; t < 2; t++) {
                        mma16816(Dn[t][2 * vp],     af[t], vb[0], vb[1]);
                        mma16816(Dn[t][2 * vp + 1], af[t], vb[2], vb[3]);
                    }
                }
            }
            __syncthreads();
        }

        // denominators: reduce over the 4 lanes of each row
        float inv[2][2];
#pragma unroll
        for (int t = 0; t < 2; t++)
#pragma unroll
            for (int h = 0; h < 2; h++) {
                float d = den[t][h];
                d += __shfl_xor_sync(0xffffffffu, d, 1);
                d += __shfl_xor_sync(0xffffffffu, d, 2);
                inv[t][h] = 1.f / d;
            }

        // normalize + accumulate into g_acc[b][c][n]
        float* accb = g_acc + (size_t)b * C_ * N_;
        int cb0 = cbase + 2 * (lane & 3);
#pragma unroll
        for (int t = 0; t < 2; t++) {
            int n0 = itile + wrow + t * 16 + (lane >> 2);
#pragma unroll
            for (int ct = 0; ct < 16; ct++) {
                int c = cb0 + 8 * ct;
                float* p0 = accb + (size_t)c * N_ + n0;
                float* p1 = p0 + N_;
                float v0 = Dn[t][ct][0] * inv[t][0], v1 = Dn[t][ct][1] * inv[t][0];
                float v2 = Dn[t][ct][2] * inv[t][1], v3 = Dn[t][ct][3] * inv[t][1];
                if (kk == 0) {
                    p0[0] = v0; p1[0] = v1; p0[8] = v2; p1[8] = v3;
                } else {
                    p0[0] += v0; p1[0] += v1; p0[8] += v2; p1[8] += v3;
                }
            }
        }
    }
}

// ---------------------------------------------------------------------------
// q/k projection via bf16 tensor cores: out[z][n][o] (o=32) = x^T.W^T + b
constexpr int PXROW = 144;   // 64 bf16 = 128B + 16 pad
constexpr int PWROW = 144;

__global__ void __launch_bounds__(128, 4) proj_qk_kernel(const float* __restrict__ x,
                                                         const float* __restrict__ W,
                                                         const float* __restrict__ bias,
                                                         int which) {
    __shared__ char sm[128 * PXROW + 32 * PWROW];
    uint32_t xt_b = smem_u32(sm);
    uint32_t wt_b = xt_b + 128 * PXROW;
    int tid = threadIdx.x, wid = tid >> 5, lane = tid & 31;
    int z = blockIdx.z;
    int n0 = blockIdx.x * 128;
    int wrow = wid * 32;
    const float* xb = x + (size_t)z * C_ * N_;

    uint32_t xaddr = xt_b + (wrow + (lane & 15)) * PXROW + ((lane >> 4) & 1) * 16;
    uint32_t waddr = wt_b + ((lane >> 4) * 8 + (lane & 7)) * PWROW + ((lane >> 3) & 1) * 16;

    float s[2][4][4];
#pragma unroll
    for (int t = 0; t < 2; t++)
#pragma unroll
        for (int j = 0; j < 4; j++) {
            int o = j * 8 + 2 * (lane & 3);
            float b0 = bias[o], b1 = bias[o + 1];
            s[t][j][0] = b0; s[t][j][1] = b1;
            s[t][j][2] = b0; s[t][j][3] = b1;
        }

    for (int ks = 0; ks < 4; ks++) {
        int k0 = ks * 64;
        __syncthreads();
        // x^T tile [128n][64k] fp32 -> bf16 (transpose during load)
        {
            int n = tid;
#pragma unroll
            for (int kg = 0; kg < 16; kg++) {
                int k = k0 + kg * 4;
                float a0 = xb[(size_t)(k + 0) * N_ + n0 + n];
                float a1 = xb[(size_t)(k + 1) * N_ + n0 + n];
                float a2 = xb[(size_t)(k + 2) * N_ + n0 + n];
                float a3 = xb[(size_t)(k + 3) * N_ + n0 + n];
                uint32_t lo = packbf2(a0, a1), hi = packbf2(a2, a3);
                uint32_t d = xt_b + n * PXROW + kg * 8;
                asm volatile("st.shared.v2.b32 [%0], {%1, %2};" :: "r"(d), "r"(lo), "r"(hi));
            }
        }
        // W tile [32o][64k] fp32 -> bf16
#pragma unroll
        for (int i = 0; i < 4; i++) {
            int e = tid + 128 * i;
            int r = e >> 4, kq = e & 15;
            float4 w4 = *(const float4*)(W + (size_t)r * C_ + k0 + kq * 4);
            uint32_t lo = packbf2(w4.x, w4.y), hi = packbf2(w4.z, w4.w);
            uint32_t d = wt_b + r * PWROW + kq * 8;
            asm volatile("st.shared.v2.b32 [%0], {%1, %2};" :: "r"(d), "r"(lo), "r"(hi));
        }
        __syncthreads();

#pragma unroll
        for (int kc = 0; kc < 4; kc++) {
            uint32_t qa[2][4];
#pragma unroll
            for (int t = 0; t < 2; t++)
                ldsm4(qa[t], xaddr + t * 16 * PXROW + kc * 32);
#pragma unroll
            for (int jp = 0; jp < 2; jp++) {
                uint32_t wb[4];
                ldsm4(wb, waddr + jp * 16 * PWROW + kc * 32);
#pragma unroll
                for (int t = 0; t < 2; t++) {
                    mma16816(s[t][2 * jp],     qa[t], wb[0], wb[1]);
                    mma16816(s[t][2 * jp + 1], qa[t], wb[2], wb[3]);
                }
            }
        }
    }

    __nv_bfloat16* dst = (which ? g_k : g_q) + ((size_t)z * N_ + n0) * C8_;
#pragma unroll
    for (int t = 0; t < 2; t++) {
        int n = wrow + t * 16 + (lane >> 2);
#pragma unroll
        for (int j = 0; j < 4; j++) {
            int o = j * 8 + 2 * (lane & 3);
            *(uint32_t*)(dst + (size_t)n * C8_ + o)       = packbf2(s[t][j][0], s[t][j][1]);
            *(uint32_t*)(dst + (size_t)(n + 8) * C8_ + o) = packbf2(s[t][j][2], s[t][j][3]);
        }
    }
}

// ---------------------------------------------------------------------------
// v projection via bf16 tensor cores: g_v[z][c][n] = Wv[c][:].x[:][n] + bv[c]
constexpr int WROW = 144;
constexpr int XROW = 144;

__global__ void __launch_bounds__(128, 2) proj_v_kernel(const float* __restrict__ xball,
                                                        const float* __restrict__ W,
                                                        const float* __restrict__ bias) {
    __shared__ char sm[128 * WROW + 128 * XROW];
    uint32_t wt_b = smem_u32(sm);
    uint32_t xt_b = wt_b + 128 * WROW;
    int tid = threadIdx.x, wid = tid >> 5, lane = tid & 31;
    int z = blockIdx.z;
    int cbase = blockIdx.y * 128;
    int n0 = blockIdx.x * 128;
    int wrow = wid * 32;
    const float* xb = xball + (size_t)z * C_ * N_;

    uint32_t waddr = wt_b + (wrow + (lane & 15)) * WROW + ((lane >> 4) & 1) * 16;
    uint32_t xaddr = xt_b + ((lane >> 4) * 8 + (lane & 7)) * XROW + ((lane >> 3) & 1) * 16;

    float acc[2][16][4];
#pragma unroll
    for (int t = 0; t < 2; t++) {
        float b0 = bias[cbase + wrow + t * 16 + (lane >> 2)];
        float b1 = bias[cbase + wrow + t * 16 + (lane >> 2) + 8];
#pragma unroll
        for (int nt = 0; nt < 16; nt++) {
            acc[t][nt][0] = b0; acc[t][nt][1] = b0;
            acc[t][nt][2] = b1; acc[t][nt][3] = b1;
        }
    }

    for (int ks = 0; ks < 4; ks++) {
        int k0 = ks * 64;
        __syncthreads();
#pragma unroll
        for (int i = 0; i < 16; i++) {
            int idx = tid + 128 * i;
            int r = idx >> 4, kq = idx & 15;
            float4 w4 = *(const float4*)(W + (size_t)(cbase + r) * C_ + k0 + kq * 4);
            uint32_t lo = packbf2(w4.x, w4.y), hi = packbf2(w4.z, w4.w);
            uint32_t d = wt_b + r * WROW + kq * 8;
            asm volatile("st.shared.v2.b32 [%0], {%1, %2};" :: "r"(d), "r"(lo), "r"(hi));
        }
        {
            int n = tid;
#pragma unroll
            for (int kg = 0; kg < 16; kg++) {
                int k = k0 + kg * 4;
                float a0 = xb[(size_t)(k + 0) * N_ + n0 + n];
                float a1 = xb[(size_t)(k + 1) * N_ + n0 + n];
                float a2 = xb[(size_t)(k + 2) * N_ + n0 + n];
                float a3 = xb[(size_t)(k + 3) * N_ + n0 + n];
                uint32_t lo = packbf2(a0, a1), hi = packbf2(a2, a3);
                uint32_t d = xt_b + n * XROW + kg * 8;
                asm volatile("st.shared.v2.b32 [%0], {%1, %2};" :: "r"(d), "r"(lo), "r"(hi));
            }
        }
        __syncthreads();

#pragma unroll
        for (int q = 0; q < 4; q++) {
            uint32_t af[2][4];
#pragma unroll
            for (int t = 0; t < 2; t++)
                ldsm4(af[t], waddr + t * 16 * WROW + q * 32);
#pragma unroll
            for (int np = 0; np < 8; np++) {
                uint32_t xb4[4];
                ldsm4(xb4, xaddr + np * 16 * XROW + q * 32);
#pragma unroll
                for (int t = 0; t < 2; t++) {
                    mma16816(acc[t][2 * np],     af[t], xb4[0], xb4[1]);
                    mma16816(acc[t][2 * np + 1], af[t], xb4[2], xb4[3]);
                }
            }
        }
    }

    __nv_bfloat16* outb = g_v + (size_t)z * C_ * N_;
#pragma unroll
    for (int t = 0; t < 2; t++) {
        int c0 = cbase + wrow + t * 16 + (lane >> 2);
#pragma unroll
        for (int nt = 0; nt < 16; nt++) {
            int n = n0 + nt * 8 + 2 * (lane & 3);
            uint32_t lo = packbf2(acc[t][nt][0], acc[t][nt][1]);
            uint32_t hi = packbf2(acc[t][nt][2], acc[t][nt][3]);
            *(uint32_t*)(outb + (size_t)c0 * N_ + n) = lo;
            *(uint32_t*)(outb + (size_t)(c0 + 8) * N_ + n) = hi;
        }
    }
}

// ---------------------------------------------------------------------------
// final: out[b][o][n] = bf[o] + sum_c (gamma*Wf[o][c])*acc + Wf[o][C+c]*xf
// 4 n-values per thread; weights in [c][16] float4-friendly smem, gamma folded
__global__ void __launch_bounds__(128) final_kernel(const float* __restrict__ xf,
                                                    const float* __restrict__ Wf,
                                                    const float* __restrict__ bf,
                                                    const float* __restrict__ gptr,
                                                    float* __restrict__ out) {
    __shared__ float Wa[256 * 16], Wx[256 * 16];
    int tid = threadIdx.x;
    int b = blockIdx.z;
    int obase = blockIdx.y * 16;
    float gamma = gptr[0];
    for (int idx = tid; idx < 4096; idx += 128) {
        int c = idx >> 4, o = idx & 15;
        Wa[idx] = Wf[(size_t)(obase + o) * 512 + c] * gamma;
        Wx[idx] = Wf[(size_t)(obase + o) * 512 + 256 + c];
    }
    __syncthreads();
    int n = blockIdx.x * 512 + tid;   // n, +128, +256, +384
    const float* xb = xf + (size_t)b * C_ * N_;
    const float* ab = g_acc + (size_t)b * C_ * N_;
    float acc[4][16];
#pragma unroll
    for (int o = 0; o < 16; o++) {
        float bv = bf[obase + o];
#pragma unroll
        for (int q = 0; q < 4; q++) acc[q][o] = bv;
    }
    for (int c = 0; c < C_; c++) {
        float av[4], xv[4];
#pragma unroll
        for (int q = 0; q < 4; q++) {
            av[q] = ab[(size_t)c * N_ + n + 128 * q];
            xv[q] = xb[(size_t)c * N_ + n + 128 * q];
        }
        const float4* wa4 = (const float4*)(Wa + c * 16);
        const float4* wx4 = (const float4*)(Wx + c * 16);
#pragma unroll
        for (int g = 0; g < 4; g++) {
            float4 wa = wa4[g], wx = wx4[g];
#pragma unroll
            for (int q = 0; q < 4; q++) {
                acc[q][g * 4 + 0] = fmaf(wa.x, av[q], acc[q][g * 4 + 0]);
                acc[q][g * 4 + 0] = fmaf(wx.x, xv[q], acc[q][g * 4 + 0]);
                acc[q][g * 4 + 1] = fmaf(wa.y, av[q], acc[q][g * 4 + 1]);
                acc[q][g * 4 + 1] = fmaf(wx.y, xv[q], acc[q][g * 4 + 1]);
                acc[q][g * 4 + 2] = fmaf(wa.z, av[q], acc[q][g * 4 + 2]);
                acc[q][g * 4 + 2] = fmaf(wx.z, xv[q], acc[q][g * 4 + 2]);
                acc[q][g * 4 + 3] = fmaf(wa.w, av[q], acc[q][g * 4 + 3]);
                acc[q][g * 4 + 3] = fmaf(wx.w, xv[q], acc[q][g * 4 + 3]);
            }
        }
    }
#pragma unroll
    for (int o = 0; o < 16; o++) {
        float* p = out + ((size_t)b * C_ + obase + o) * N_ + n;
#pragma unroll
        for (int q = 0; q < 4; q++) p[128 * q] = acc[q][o];
    }
}

// ---------------------------------------------------------------------------
extern "C" void kernel_launch(void* const* d_in, const int* in_sizes, int n_in,
                              void* d_out, int out_size) {
    const float* x_f = (const float*)d_in[0];
    const float* x_b = (const float*)d_in[1];
    const float* Wq  = (const float*)d_in[2];
    const float* bq  = (const float*)d_in[3];
    const float* Wk  = (const float*)d_in[4];
    const float* bk  = (const float*)d_in[5];
    const float* Wv  = (const float*)d_in[6];
    const float* bv  = (const float*)d_in[7];
    const float* Wf  = (const float*)d_in[8];
    const float* bf  = (const float*)d_in[9];
    const float* gm  = (const float*)d_in[10];
    float* out = (float*)d_out;

    cudaFuncSetAttribute(attn_kernel, cudaFuncAttributeMaxDynamicSharedMemorySize, SM_TOTAL);

    proj_qk_kernel<<<dim3(N_ / 128, 1, B_), 128>>>(x_f, Wk, bk, 1);
    proj_qk_kernel<<<dim3(N_ / 128, 1, K_ * B_), 128>>>(x_b, Wq, bq, 0);
    proj_v_kernel<<<dim3(N_ / 128, C_ / 128, K_ * B_), 128>>>(x_b, Wv, bv);
    attn_kernel<<<dim3(N_ / TI, C_ / TC, B_), 128, SM_TOTAL>>>();
    final_kernel<<<dim3(N_ / 512, C_ / 16, B_), 128>>>(x_f, Wf, bf, gm, out);
}